// round 8
// baseline (speedup 1.0000x reference)
#include <cuda_runtime.h>
#include <cstdint>

#define BP 512
#define CC 96
#define TT 128
#define JJ 24
#define ZZ 256
#define CT 12288
#define N2 1024

__device__ float  g_qs[(size_t)N2 * CT];    // decoded motion (1024 x 12288)
__device__ float  g_dqs[(size_t)BP * CT];   // d f / d qs (k=0 rows)
__device__ float  g_grad[(size_t)BP * ZZ];  // grad wrt latent[:,0]
__device__ double g_acc[6];                 // 0 root 1 joints 2 fk 3 kld 4 disp 5 cons

// ---------------------------------------------------------------------------
__global__ void zero_kernel() {
    int i = blockIdx.x * blockDim.x + threadIdx.x;
    if (i < BP * ZZ) g_grad[i] = 0.f;
    if (i < 6)       g_acc[i] = 0.0;
}

// ---------------------------------------------------------------------------
__device__ __forceinline__ float blockReduce(float v, float* sm) {
#pragma unroll
    for (int o = 16; o > 0; o >>= 1) v += __shfl_down_sync(0xffffffffu, v, o);
    int lane = threadIdx.x & 31, w = threadIdx.x >> 5;
    if (lane == 0) sm[w] = v;
    __syncthreads();
    v = 0.f;
    if (threadIdx.x < 32) {
        int nw = (blockDim.x + 31) >> 5;
        v = (threadIdx.x < nw) ? sm[threadIdx.x] : 0.f;
#pragma unroll
        for (int o = 16; o > 0; o >>= 1) v += __shfl_down_sync(0xffffffffu, v, o);
    }
    return v;
}

// ---------------------------------------------------------------------------
__device__ __forceinline__ void cp16(uint32_t dst, const void* src) {
    asm volatile("cp.async.ca.shared.global [%0], [%1], 16;\n" :: "r"(dst), "l"(src));
}
#define CP_COMMIT() asm volatile("cp.async.commit_group;\n")
#define CP_WAIT1()  asm volatile("cp.async.wait_group 1;\n")

__device__ __forceinline__ void mma_tf32(float& c0, float& c1, float& c2, float& c3,
                                         uint32_t a0, uint32_t a1, uint32_t a2, uint32_t a3,
                                         uint32_t b0, uint32_t b1)
{
    asm volatile("mma.sync.aligned.m16n8k8.row.col.f32.tf32.tf32.f32 "
                 "{%0,%1,%2,%3}, {%4,%5,%6,%7}, {%8,%9}, {%0,%1,%2,%3};"
                 : "+f"(c0), "+f"(c1), "+f"(c2), "+f"(c3)
                 : "r"(a0), "r"(a1), "r"(a2), "r"(a3), "r"(b0), "r"(b1));
}

// ---------------------------------------------------------------------------
// GEMM1 (tf32, cp.async 2-stage, high-occupancy): qs = lat(1024x256)@W + base
// CTA tile 64(M)x128(N), BK=32; 8 warps (2m x 4n); warp tile 32x32.
__global__ __launch_bounds__(256, 4) void gemm1_tc(const float* __restrict__ A,
                                                   const float* __restrict__ B,
                                                   const float* __restrict__ base)
{
    extern __shared__ float smem[];
    float* Asm = smem;               // 2 * 2048  ([m][32] swizzled)
    float* Bsm = smem + 4096;        // 2 * 4352  ([k][136] padded)
    const uint32_t sA = (uint32_t)__cvta_generic_to_shared(Asm);
    const uint32_t sB = (uint32_t)__cvta_generic_to_shared(Bsm);

    const int tid  = threadIdx.x;
    const int lane = tid & 31;
    const int wid  = tid >> 5;
    const int wm   = wid & 1;
    const int wn   = wid >> 1;
    const int g    = lane >> 2;
    const int tg   = lane & 3;
    const int bm   = blockIdx.y << 6;
    const int bn   = blockIdx.x << 7;

    float acc[2][4][4];
#pragma unroll
    for (int i = 0; i < 2; i++)
#pragma unroll
        for (int j = 0; j < 4; j++)
#pragma unroll
            for (int c = 0; c < 4; c++) acc[i][j][c] = 0.f;

    auto loadTiles = [&](int kb, int s) {
#pragma unroll
        for (int it = 0; it < 2; it++) {
            int f = tid + it * 256;
            int m = f >> 3, cq = f & 7;
            int dc = cq ^ (m & 7);
            cp16(sA + ((s * 2048 + m * 32 + dc * 4) << 2),
                 &A[(size_t)(bm + m) * ZZ + kb + cq * 4]);
        }
#pragma unroll
        for (int it = 0; it < 4; it++) {
            int f = tid + it * 256;
            int k = f >> 5, nq = f & 31;
            cp16(sB + ((s * 4352 + k * 136 + nq * 4) << 2),
                 &B[(size_t)(kb + k) * CT + bn + nq * 4]);
        }
    };

    loadTiles(0, 0);
    CP_COMMIT();

    const int NK = ZZ / 32;  // 8
    for (int kt = 0; kt < NK; kt++) {
        if (kt + 1 < NK) loadTiles((kt + 1) * 32, (kt + 1) & 1);
        CP_COMMIT();
        CP_WAIT1();
        __syncthreads();

        const uint32_t* as = reinterpret_cast<const uint32_t*>(Asm + (kt & 1) * 2048);
        const uint32_t* bs = reinterpret_cast<const uint32_t*>(Bsm + (kt & 1) * 4352);
#pragma unroll
        for (int ks = 0; ks < 4; ks++) {
            const int kc = ks * 8;
            const int sw0 = (((2 * ks)     ^ g) << 2) + tg;
            const int sw1 = (((2 * ks + 1) ^ g) << 2) + tg;
            uint32_t afr[2][4];
#pragma unroll
            for (int i = 0; i < 2; i++) {
                int r0 = wm * 32 + i * 16 + g;
                afr[i][0] = as[r0 * 32 + sw0];
                afr[i][1] = as[(r0 + 8) * 32 + sw0];
                afr[i][2] = as[r0 * 32 + sw1];
                afr[i][3] = as[(r0 + 8) * 32 + sw1];
            }
            uint32_t bfr[4][2];
#pragma unroll
            for (int j = 0; j < 4; j++) {
                int c0 = wn * 32 + j * 8 + g;
                bfr[j][0] = bs[(kc + tg) * 136 + c0];
                bfr[j][1] = bs[(kc + tg + 4) * 136 + c0];
            }
#pragma unroll
            for (int i = 0; i < 2; i++)
#pragma unroll
                for (int j = 0; j < 4; j++)
                    mma_tf32(acc[i][j][0], acc[i][j][1], acc[i][j][2], acc[i][j][3],
                             afr[i][0], afr[i][1], afr[i][2], afr[i][3],
                             bfr[j][0], bfr[j][1]);
        }
        __syncthreads();
    }

#pragma unroll
    for (int i = 0; i < 2; i++) {
#pragma unroll
        for (int j = 0; j < 4; j++) {
            int row0 = bm + wm * 32 + i * 16 + g;
            int col  = bn + wn * 32 + j * 8 + 2 * tg;
            {
                size_t o = (size_t)row0 * CT + col;
                float2 bv = *reinterpret_cast<const float2*>(&base[o]);
                float2 ov; ov.x = acc[i][j][0] + bv.x; ov.y = acc[i][j][1] + bv.y;
                *reinterpret_cast<float2*>(&g_qs[o]) = ov;
            }
            {
                size_t o = (size_t)(row0 + 8) * CT + col;
                float2 bv = *reinterpret_cast<const float2*>(&base[o]);
                float2 ov; ov.x = acc[i][j][2] + bv.x; ov.y = acc[i][j][3] + bv.y;
                *reinterpret_cast<float2*>(&g_qs[o]) = ov;
            }
        }
    }
}

// ---------------------------------------------------------------------------
// GEMM2 (tf32, 2-stage, split-K=32, high-occupancy): grad[m,z] += dqs[m,:].W[z,:]
// CTA tile 64(M)x128(Z); both operands k-contiguous [row][32] swizzled.
__global__ __launch_bounds__(256, 4) void gemm2_tc(const float* __restrict__ W)
{
    extern __shared__ float smem[];
    float* Asm = smem;               // 2 * 2048 (dqs, [m][32])
    float* Wsm = smem + 4096;        // 2 * 4096 (W,   [z][32])
    const uint32_t sA = (uint32_t)__cvta_generic_to_shared(Asm);
    const uint32_t sW = (uint32_t)__cvta_generic_to_shared(Wsm);

    const int tid  = threadIdx.x;
    const int lane = tid & 31;
    const int wid  = tid >> 5;
    const int wm   = wid & 1;
    const int wn   = wid >> 1;
    const int g    = lane >> 2;
    const int tg   = lane & 3;
    const int bm   = blockIdx.y << 6;
    const int bn   = blockIdx.x << 7;
    const int k0s  = blockIdx.z * (CT / 32);   // 384 per split

    float acc[2][4][4];
#pragma unroll
    for (int i = 0; i < 2; i++)
#pragma unroll
        for (int j = 0; j < 4; j++)
#pragma unroll
            for (int c = 0; c < 4; c++) acc[i][j][c] = 0.f;

    auto loadTiles = [&](int kb, int s) {
#pragma unroll
        for (int it = 0; it < 2; it++) {
            int f = tid + it * 256;
            int m = f >> 3, cq = f & 7;
            int dc = cq ^ (m & 7);
            cp16(sA + ((s * 2048 + m * 32 + dc * 4) << 2),
                 &g_dqs[(size_t)(bm + m) * CT + kb + cq * 4]);
        }
#pragma unroll
        for (int it = 0; it < 4; it++) {
            int f = tid + it * 256;
            int z = f >> 3, cq = f & 7;
            int dc = cq ^ (z & 7);
            cp16(sW + ((s * 4096 + z * 32 + dc * 4) << 2),
                 &W[(size_t)(bn + z) * CT + kb + cq * 4]);
        }
    };

    loadTiles(k0s, 0);
    CP_COMMIT();

    const int NK = (CT / 32) / 32;  // 12
    for (int kt = 0; kt < NK; kt++) {
        if (kt + 1 < NK) loadTiles(k0s + (kt + 1) * 32, (kt + 1) & 1);
        CP_COMMIT();
        CP_WAIT1();
        __syncthreads();

        const uint32_t* as = reinterpret_cast<const uint32_t*>(Asm + (kt & 1) * 2048);
        const uint32_t* ws = reinterpret_cast<const uint32_t*>(Wsm + (kt & 1) * 4096);
#pragma unroll
        for (int ks = 0; ks < 4; ks++) {
            const int sw0 = (((2 * ks)     ^ g) << 2) + tg;
            const int sw1 = (((2 * ks + 1) ^ g) << 2) + tg;
            uint32_t afr[2][4];
#pragma unroll
            for (int i = 0; i < 2; i++) {
                int r0 = wm * 32 + i * 16 + g;
                afr[i][0] = as[r0 * 32 + sw0];
                afr[i][1] = as[(r0 + 8) * 32 + sw0];
                afr[i][2] = as[r0 * 32 + sw1];
                afr[i][3] = as[(r0 + 8) * 32 + sw1];
            }
            uint32_t bfr[4][2];
#pragma unroll
            for (int j = 0; j < 4; j++) {
                int c0 = wn * 32 + j * 8 + g;   // c0&7 == g -> conflict-free
                bfr[j][0] = ws[c0 * 32 + sw0];
                bfr[j][1] = ws[c0 * 32 + sw1];
            }
#pragma unroll
            for (int i = 0; i < 2; i++)
#pragma unroll
                for (int j = 0; j < 4; j++)
                    mma_tf32(acc[i][j][0], acc[i][j][1], acc[i][j][2], acc[i][j][3],
                             afr[i][0], afr[i][1], afr[i][2], afr[i][3],
                             bfr[j][0], bfr[j][1]);
        }
        __syncthreads();
    }

#pragma unroll
    for (int i = 0; i < 2; i++)
#pragma unroll
        for (int j = 0; j < 4; j++) {
            int row0 = bm + wm * 32 + i * 16 + g;
            int col  = bn + wn * 32 + j * 8 + 2 * tg;
            atomicAdd(&g_grad[(size_t)row0 * ZZ + col],           acc[i][j][0]);
            atomicAdd(&g_grad[(size_t)row0 * ZZ + col + 1],       acc[i][j][1]);
            atomicAdd(&g_grad[(size_t)(row0 + 8) * ZZ + col],     acc[i][j][2]);
            atomicAdd(&g_grad[(size_t)(row0 + 8) * ZZ + col + 1], acc[i][j][3]);
        }
}

// ---------------------------------------------------------------------------
__device__ __forceinline__ void qrot(const float* __restrict__ q,
                                     const float* __restrict__ v,
                                     float* __restrict__ r)
{
    float w = q[0], x = q[1], y = q[2], z = q[3];
    float inv = 1.0f / (w * w + x * x + y * y + z * z);
    float a = w * w - (x * x + y * y + z * z);
    float d = 2.0f * (x * v[0] + y * v[1] + z * v[2]);
    float cx = y * v[2] - z * v[1];
    float cy = z * v[0] - x * v[2];
    float cz = x * v[1] - y * v[0];
    float tw = 2.0f * w;
    r[0] = (a * v[0] + d * x + tw * cx) * inv;
    r[1] = (a * v[1] + d * y + tw * cy) * inv;
    r[2] = (a * v[2] + d * z + tw * cz) * inv;
}

__device__ __forceinline__ void qrot_bwd(const float* __restrict__ q,
                                         const float* __restrict__ v,
                                         const float* __restrict__ g,
                                         float& dw, float& dx, float& dy, float& dz)
{
    float w = q[0], x = q[1], y = q[2], z = q[3];
    float inv = 1.0f / (w * w + x * x + y * y + z * z);
    float a = w * w - (x * x + y * y + z * z);
    float dd = 2.0f * (x * v[0] + y * v[1] + z * v[2]);
    float cx = y * v[2] - z * v[1];
    float cy = z * v[0] - x * v[2];
    float cz = x * v[1] - y * v[0];
    float tw = 2.0f * w;
    float r0 = (a * v[0] + dd * x + tw * cx) * inv;
    float r1 = (a * v[1] + dd * y + tw * cy) * inv;
    float r2 = (a * v[2] + dd * z + tw * cz) * inv;
    float c1 = v[0] * g[0] + v[1] * g[1] + v[2] * g[2];
    float c2 = x * g[0] + y * g[1] + z * g[2];
    float c3 = 0.5f * dd;
    float gr = g[0] * r0 + g[1] * r1 + g[2] * r2;
    float cg = cx * g[0] + cy * g[1] + cz * g[2];
    float s = 2.0f * inv;
    float vgx = v[1] * g[2] - v[2] * g[1];
    float vgy = v[2] * g[0] - v[0] * g[2];
    float vgz = v[0] * g[1] - v[1] * g[0];
    dw += s * (w * c1 + cg - w * gr);
    dx += s * (-c1 * x + c2 * v[0] + c3 * g[0] + w * vgx - gr * x);
    dy += s * (-c1 * y + c2 * v[1] + c3 * g[1] + w * vgy - gr * y);
    dz += s * (-c1 * z + c2 * v[2] + c3 * g[2] + w * vgz - gr * z);
}

// ---------------------------------------------------------------------------
// Pose kernel, k-split (round-7 structure, measured good).
__global__ __launch_bounds__(256) void pose_kernel(const float* __restrict__ tgt,
                                                   const float* __restrict__ stdq,
                                                   const float* __restrict__ meanq,
                                                   const float* __restrict__ offs)
{
    __shared__ float s_std[CC], s_mean[CC], s_off[JJ * 3];
    __shared__ float s_buf[72 * 128];
    __shared__ float s_red[32];
    const int b  = blockIdx.x;
    const int t  = threadIdx.x;
    const int tk = t >> 7;
    const int tt = t & 127;
    if (t < CC) { s_std[t] = stdq[t]; s_mean[t] = meanq[t]; }
    if (t >= 128 && t < 128 + JJ * 3) s_off[t - 128] = offs[b * JJ * 3 + (t - 128)];
    __syncthreads();

    float accR = 0.f, accJ = 0.f, accF = 0.f;

    const float* dbase = g_qs + (size_t)(b * 2 + tk) * CT + tt;
    const float* tbase = tgt + (size_t)(b * 2 + tk) * (2 * CT) + tt;

    {
#pragma unroll
        for (int i = 0; i < 4; i++) {
            float df = dbase[(size_t)i * TT] - tbase[(size_t)i * TT];
            accR += df * df;
        }
        const int leaves[5] = { 10, 11, 15, 22, 23 };
#pragma unroll
        for (int e = 0; e < 5; e++) {
            int j = leaves[e];
#pragma unroll
            for (int i = 0; i < 4; i++) {
                float df = dbase[(size_t)(4 * j + i) * TT] - tbase[(size_t)(8 * j + i) * TT];
                accJ += df * df;
            }
        }
    }

    float pd[72];
    {
        float qD[4], qT[4];
        float pDx, pDy, pDz, pTx, pTy, pTz;

        auto loadPair = [&](int j) {
#pragma unroll
            for (int i = 0; i < 4; i++) {
                int c = 4 * j + i;
                float d  = dbase[(size_t)c * TT];
                float tr = tbase[(size_t)(8 * j + i) * TT];
                float df = d - tr;
                accJ += df * df;
                qD[i] = d * s_std[c] + s_mean[c];
                qT[i] = tr * s_std[c] + s_mean[c];
            }
        };
        auto step = [&](int j) {
            const float* v = s_off + 3 * j;
            float r[3];
            qrot(qD, v, r); pDx += r[0]; pDy += r[1]; pDz += r[2];
            qrot(qT, v, r); pTx += r[0]; pTy += r[1]; pTz += r[2];
            float dx = pDx - pTx, dy = pDy - pTy, dz = pDz - pTz;
            accF += dx * dx + dy * dy + dz * dz;
            pd[3 * j + 0] = pDx; pd[3 * j + 1] = pDy; pd[3 * j + 2] = pDz;
        };
        auto reset = [&]() {
            pDx = pDy = pDz = pTx = pTy = pTz = 0.f;
            qD[0] = 1.f; qD[1] = qD[2] = qD[3] = 0.f;
            qT[0] = 1.f; qT[1] = qT[2] = qT[3] = 0.f;
        };

        reset();
        step(1); loadPair(1); step(4); loadPair(4); step(7); loadPair(7); step(10);
        reset();
        step(2); loadPair(2); step(5); loadPair(5); step(8); loadPair(8); step(11);
        reset();
        step(3); loadPair(3); step(6); loadPair(6); step(9); loadPair(9);
        float sp[6] = { pDx, pDy, pDz, pTx, pTy, pTz };
        float sqD[4] = { qD[0], qD[1], qD[2], qD[3] };
        float sqT[4] = { qT[0], qT[1], qT[2], qT[3] };
        step(12); loadPair(12); step(15);
        pDx = sp[0]; pDy = sp[1]; pDz = sp[2]; pTx = sp[3]; pTy = sp[4]; pTz = sp[5];
        qD[0] = sqD[0]; qD[1] = sqD[1]; qD[2] = sqD[2]; qD[3] = sqD[3];
        qT[0] = sqT[0]; qT[1] = sqT[1]; qT[2] = sqT[2]; qT[3] = sqT[3];
        step(13); loadPair(13); step(16); loadPair(16); step(18); loadPair(18);
        step(20); loadPair(20); step(22);
        pDx = sp[0]; pDy = sp[1]; pDz = sp[2]; pTx = sp[3]; pTy = sp[4]; pTz = sp[5];
        qD[0] = sqD[0]; qD[1] = sqD[1]; qD[2] = sqD[2]; qD[3] = sqD[3];
        qT[0] = sqT[0]; qT[1] = sqT[1]; qT[2] = sqT[2]; qT[3] = sqT[3];
        step(14); loadPair(14); step(17); loadPair(17); step(19); loadPair(19);
        step(21); loadPair(21); step(23);
    }

    if (tk == 1) {
#pragma unroll
        for (int r = 3; r < 72; r++) s_buf[r * 128 + tt] = pd[r];
    }
    __syncthreads();

    if (tk == 0) {
#pragma unroll
        for (int r = 3; r < 72; r++) pd[r] = 2.f * (pd[r] - s_buf[r * 128 + tt]);
        const int ch[20] = { 23,22,21,20,19,18,17,16,15,14,13,12,11,10,9,8,7,6,5,4 };
        const int pa[20] = { 21,20,19,18,17,16,14,13,12, 9, 9, 9, 8, 7, 6, 5, 4, 3, 2, 1 };
#pragma unroll
        for (int e = 0; e < 20; e++) {
            int cj = ch[e], pj = pa[e];
            pd[3 * pj + 0] += pd[3 * cj + 0];
            pd[3 * pj + 1] += pd[3 * cj + 1];
            pd[3 * pj + 2] += pd[3 * cj + 2];
        }
#pragma unroll
        for (int r = 3; r < 72; r++) s_buf[r * 128 + tt] = pd[r];
    }
    __syncthreads();
    if (tk == 1) {
#pragma unroll
        for (int r = 3; r < 72; r++) pd[r] = s_buf[r * 128 + tt];
    }

    float* outp = g_dqs + (size_t)b * CT + tt;
    const float* dbase0 = g_qs + (size_t)(b * 2) * CT + tt;
    auto doParent = [&](int p, int c0, int c1, int c2) {
        float q[4];
#pragma unroll
        for (int i = 0; i < 4; i++) {
            int c = 4 * p + i;
            q[i] = dbase0[(size_t)c * TT] * s_std[c] + s_mean[c];
        }
        float dw = 0.f, dx = 0.f, dy = 0.f, dz = 0.f;
        qrot_bwd(q, s_off + 3 * c0, pd + 3 * c0, dw, dx, dy, dz);
        if (c1 >= 0) qrot_bwd(q, s_off + 3 * c1, pd + 3 * c1, dw, dx, dy, dz);
        if (c2 >= 0) qrot_bwd(q, s_off + 3 * c2, pd + 3 * c2, dw, dx, dy, dz);
        outp[(size_t)(4 * p + 0) * TT] = dw * s_std[4 * p + 0];
        outp[(size_t)(4 * p + 1) * TT] = dx * s_std[4 * p + 1];
        outp[(size_t)(4 * p + 2) * TT] = dy * s_std[4 * p + 2];
        outp[(size_t)(4 * p + 3) * TT] = dz * s_std[4 * p + 3];
    };
    if (tk == 0) {
        const int zj[3] = { 0, 10, 11 };
#pragma unroll
        for (int e = 0; e < 3; e++)
#pragma unroll
            for (int i = 0; i < 4; i++)
                outp[(size_t)(4 * zj[e] + i) * TT] = 0.f;
        doParent(1, 4, -1, -1);  doParent(2, 5, -1, -1);  doParent(3, 6, -1, -1);
        doParent(4, 7, -1, -1);  doParent(5, 8, -1, -1);  doParent(6, 9, -1, -1);
        doParent(7, 10, -1, -1); doParent(8, 11, -1, -1);
        doParent(9, 12, 13, 14);
    } else {
        const int zj[3] = { 15, 22, 23 };
#pragma unroll
        for (int e = 0; e < 3; e++)
#pragma unroll
            for (int i = 0; i < 4; i++)
                outp[(size_t)(4 * zj[e] + i) * TT] = 0.f;
        doParent(12, 15, -1, -1); doParent(13, 16, -1, -1); doParent(14, 17, -1, -1);
        doParent(16, 18, -1, -1); doParent(17, 19, -1, -1); doParent(18, 20, -1, -1);
        doParent(19, 21, -1, -1); doParent(20, 22, -1, -1); doParent(21, 23, -1, -1);
    }

    float r = blockReduce(accR, s_red);
    if (threadIdx.x == 0) atomicAdd(&g_acc[0], (double)r);
    __syncthreads();
    r = blockReduce(accJ, s_red);
    if (threadIdx.x == 0) atomicAdd(&g_acc[1], (double)r);
    __syncthreads();
    r = blockReduce(accF, s_red);
    if (threadIdx.x == 0) atomicAdd(&g_acc[2], (double)r);
}

// ---------------------------------------------------------------------------
// cons + disp + KLD reductions (misc folded in; runs after gemm2)
__global__ void cons_kernel(const float* __restrict__ lat,
                            const float* __restrict__ id, const float* __restrict__ td,
                            const float* __restrict__ mu, const float* __restrict__ lv)
{
    __shared__ float s_red[32];
    int i = blockIdx.x * blockDim.x + threadIdx.x;
    int stride = gridDim.x * blockDim.x;   // 131072
    int b = i >> 8, z = i & 255;
    float d = lat[(size_t)(2 * b) * ZZ + z] - g_grad[i] - lat[(size_t)(2 * b + 1) * ZZ + z];
    float sc = d * d;
    float sd = 0.f, sk = 0.f;
    for (int k = i; k < BP * 2 * 3 * TT; k += stride) { float df = id[k] - td[k]; sd += df * df; }
    for (int k = i; k < N2 * ZZ; k += stride) {
        float m = mu[k], l = lv[k];
        sk += 1.0f + l - m * m - expf(l);
    }
    float r = blockReduce(sc, s_red);
    if (threadIdx.x == 0) atomicAdd(&g_acc[5], (double)r);
    __syncthreads();
    r = blockReduce(sd, s_red);
    if (threadIdx.x == 0) atomicAdd(&g_acc[4], (double)r);
    __syncthreads();
    r = blockReduce(sk, s_red);
    if (threadIdx.x == 0) atomicAdd(&g_acc[3], (double)r);
}

// ---------------------------------------------------------------------------
__global__ void finalize_kernel(float* out)
{
    out[0] = (float)(-0.5 * g_acc[3] / 1024.0) * 0.001f;
    out[1] = (float)(g_acc[0] / 524288.0);
    out[2] = (float)(g_acc[4] / 393216.0);
    out[3] = (float)(g_acc[5] / 131072.0) * 0.1f;
    out[4] = (float)(g_acc[2] / 9437184.0) * 0.1f;
    out[5] = (float)(g_acc[1] / 12058624.0);
}

// ---------------------------------------------------------------------------
extern "C" void kernel_launch(void* const* d_in, const int* in_sizes, int n_in,
                              void* d_out, int out_size)
{
    const float* base  = (const float*)d_in[0];
    const float* tgt   = (const float*)d_in[1];
    const float* idisp = (const float*)d_in[2];
    const float* tdisp = (const float*)d_in[3];
    const float* mu    = (const float*)d_in[4];
    const float* lv    = (const float*)d_in[5];
    const float* lat   = (const float*)d_in[6];
    const float* W     = (const float*)d_in[7];
    const float* meanq = (const float*)d_in[8];
    const float* stdq  = (const float*)d_in[9];
    const float* offs  = (const float*)d_in[10];
    float* out = (float*)d_out;

    cudaFuncSetAttribute(gemm1_tc, cudaFuncAttributeMaxDynamicSharedMemorySize, 51200);
    cudaFuncSetAttribute(gemm2_tc, cudaFuncAttributeMaxDynamicSharedMemorySize, 49152);

    zero_kernel<<<(BP * ZZ + 255) / 256, 256>>>();
    gemm1_tc<<<dim3(96, 16), 256, 51200>>>(lat, W, base);
    pose_kernel<<<BP, 256>>>(tgt, stdq, meanq, offs);
    gemm2_tc<<<dim3(2, 8, 32), 256, 49152>>>(W);
    cons_kernel<<<512, 256>>>(lat, idisp, tdisp, mu, lv);
    finalize_kernel<<<1, 1>>>(out);
}

// round 9
// speedup vs baseline: 1.2430x; 1.2430x over previous
#include <cuda_runtime.h>
#include <cuda_bf16.h>
#include <cstdint>

#define BP 512
#define CC 96
#define TT 128
#define JJ 24
#define ZZ 256
#define CT 12288
#define N2 1024

__device__ float          g_qs[(size_t)N2 * CT];     // decoded motion fp32
__device__ __nv_bfloat16  g_dqsb[(size_t)BP * CT];   // d f / d qs (bf16)
__device__ float          g_grad[(size_t)BP * ZZ];   // grad wrt latent[:,0]
__device__ double         g_acc[6];                  // root joints fk kld disp cons
__device__ __nv_bfloat16  g_W2[(size_t)ZZ * CT];     // W bf16, [z][ct]
__device__ uint32_t       g_W1[(size_t)(ZZ / 2) * CT]; // W bf16 k-pair packed [k2][n]
__device__ __nv_bfloat16  g_latb[(size_t)N2 * ZZ];   // latent bf16

// ---------------------------------------------------------------------------
__global__ void zero_kernel() {
    int i = blockIdx.x * blockDim.x + threadIdx.x;
    if (i < BP * ZZ) g_grad[i] = 0.f;
    if (i < 6)       g_acc[i] = 0.0;
}

// ---------------------------------------------------------------------------
// bf16 conversions: W (two layouts) + latent
__global__ void cvt_kernel(const float* __restrict__ W, const float* __restrict__ lat)
{
    const int NW  = (ZZ * CT) / 2;       // 1572864 float2 pairs -> g_W2
    const int NW1 = (ZZ / 2) * CT;       // 1572864 packed words -> g_W1
    const int NL  = (N2 * ZZ) / 2;       // 131072 pairs -> g_latb
    int i = blockIdx.x * blockDim.x + threadIdx.x;
    if (i < NW) {
        float2 v = reinterpret_cast<const float2*>(W)[i];
        reinterpret_cast<__nv_bfloat162*>(g_W2)[i] = __floats2bfloat162_rn(v.x, v.y);
    } else if (i < NW + NW1) {
        int j = i - NW;
        int k2 = j / CT, n = j - k2 * CT;
        float lo = W[(size_t)(2 * k2) * CT + n];
        float hi = W[(size_t)(2 * k2 + 1) * CT + n];
        __nv_bfloat162 h = __floats2bfloat162_rn(lo, hi);
        g_W1[j] = *reinterpret_cast<uint32_t*>(&h);
    } else if (i < NW + NW1 + NL) {
        int j = i - NW - NW1;
        float2 v = reinterpret_cast<const float2*>(lat)[j];
        reinterpret_cast<__nv_bfloat162*>(g_latb)[j] = __floats2bfloat162_rn(v.x, v.y);
    }
}

// ---------------------------------------------------------------------------
__device__ __forceinline__ float blockReduce(float v, float* sm) {
#pragma unroll
    for (int o = 16; o > 0; o >>= 1) v += __shfl_down_sync(0xffffffffu, v, o);
    int lane = threadIdx.x & 31, w = threadIdx.x >> 5;
    if (lane == 0) sm[w] = v;
    __syncthreads();
    v = 0.f;
    if (threadIdx.x < 32) {
        int nw = (blockDim.x + 31) >> 5;
        v = (threadIdx.x < nw) ? sm[threadIdx.x] : 0.f;
#pragma unroll
        for (int o = 16; o > 0; o >>= 1) v += __shfl_down_sync(0xffffffffu, v, o);
    }
    return v;
}

// ---------------------------------------------------------------------------
__device__ __forceinline__ void cp16(uint32_t dst, const void* src) {
    asm volatile("cp.async.ca.shared.global [%0], [%1], 16;\n" :: "r"(dst), "l"(src));
}
#define CP_COMMIT() asm volatile("cp.async.commit_group;\n")
#define CP_WAIT1()  asm volatile("cp.async.wait_group 1;\n")

__device__ __forceinline__ void mma_bf16(float& c0, float& c1, float& c2, float& c3,
                                         uint32_t a0, uint32_t a1, uint32_t a2, uint32_t a3,
                                         uint32_t b0, uint32_t b1)
{
    asm volatile("mma.sync.aligned.m16n8k16.row.col.f32.bf16.bf16.f32 "
                 "{%0,%1,%2,%3}, {%4,%5,%6,%7}, {%8,%9}, {%0,%1,%2,%3};"
                 : "+f"(c0), "+f"(c1), "+f"(c2), "+f"(c3)
                 : "r"(a0), "r"(a1), "r"(a2), "r"(a3), "r"(b0), "r"(b1));
}

// ---------------------------------------------------------------------------
// GEMM1 (bf16 m16n8k16, cp.async 2-stage): g_qs = latb(1024x256)@W1 + base
// BM=128 BN=128 BK=32; 8 warps (2m x 4n); warp tile 64x32.
// As: [m][20 words] (32 bf16 + pad, conflict-free 20-stride). Bs: [k2][136].
__global__ __launch_bounds__(256, 2) void gemm1_tc(const float* __restrict__ base)
{
    extern __shared__ uint32_t smem[];
    uint32_t* AsU = smem;                 // 2 * 2560
    uint32_t* BsU = smem + 5120;          // 2 * 2176
    const uint32_t sA = (uint32_t)__cvta_generic_to_shared(AsU);
    const uint32_t sB = (uint32_t)__cvta_generic_to_shared(BsU);

    const int tid  = threadIdx.x;
    const int lane = tid & 31;
    const int wid  = tid >> 5;
    const int wm   = wid & 1;
    const int wn   = wid >> 1;
    const int g    = lane >> 2;
    const int tg   = lane & 3;
    const int bm   = blockIdx.y << 7;
    const int bn   = blockIdx.x << 7;

    float acc[4][4][4];
#pragma unroll
    for (int i = 0; i < 4; i++)
#pragma unroll
        for (int j = 0; j < 4; j++)
#pragma unroll
            for (int c = 0; c < 4; c++) acc[i][j][c] = 0.f;

    auto loadTiles = [&](int kb, int s) {
#pragma unroll
        for (int it = 0; it < 2; it++) {
            int f = tid + it * 256;          // 0..511
            int m = f >> 2, cq = f & 3;      // chunk of 8 bf16
            cp16(sA + ((s * 2560 + m * 20 + cq * 4) << 2),
                 &g_latb[(size_t)(bm + m) * ZZ + kb + cq * 8]);
        }
        int kb2 = kb >> 1;
#pragma unroll
        for (int it = 0; it < 2; it++) {
            int f = tid + it * 256;          // 0..511
            int k2 = f >> 5, nq = f & 31;
            cp16(sB + ((s * 2176 + k2 * 136 + nq * 4) << 2),
                 &g_W1[(size_t)(kb2 + k2) * CT + bn + nq * 4]);
        }
    };

    loadTiles(0, 0);
    CP_COMMIT();

    const int NK = ZZ / 32;  // 8
    for (int kt = 0; kt < NK; kt++) {
        if (kt + 1 < NK) loadTiles((kt + 1) * 32, (kt + 1) & 1);
        CP_COMMIT();
        CP_WAIT1();
        __syncthreads();

        const uint32_t* as = AsU + (kt & 1) * 2560;
        const uint32_t* bs = BsU + (kt & 1) * 2176;
#pragma unroll
        for (int ks = 0; ks < 2; ks++) {
            const int kc2 = ks * 8;
            uint32_t afr[4][4];
#pragma unroll
            for (int i = 0; i < 4; i++) {
                int r0 = wm * 64 + i * 16 + g;
                afr[i][0] = as[r0 * 20 + kc2 + tg];
                afr[i][1] = as[(r0 + 8) * 20 + kc2 + tg];
                afr[i][2] = as[r0 * 20 + kc2 + tg + 4];
                afr[i][3] = as[(r0 + 8) * 20 + kc2 + tg + 4];
            }
            uint32_t bfr[4][2];
#pragma unroll
            for (int j = 0; j < 4; j++) {
                int c0 = wn * 32 + j * 8 + g;
                bfr[j][0] = bs[(kc2 + tg) * 136 + c0];
                bfr[j][1] = bs[(kc2 + tg + 4) * 136 + c0];
            }
#pragma unroll
            for (int i = 0; i < 4; i++)
#pragma unroll
                for (int j = 0; j < 4; j++)
                    mma_bf16(acc[i][j][0], acc[i][j][1], acc[i][j][2], acc[i][j][3],
                             afr[i][0], afr[i][1], afr[i][2], afr[i][3],
                             bfr[j][0], bfr[j][1]);
        }
        __syncthreads();
    }

#pragma unroll
    for (int i = 0; i < 4; i++) {
#pragma unroll
        for (int j = 0; j < 4; j++) {
            int row0 = bm + wm * 64 + i * 16 + g;
            int col  = bn + wn * 32 + j * 8 + 2 * tg;
            {
                size_t o = (size_t)row0 * CT + col;
                float2 bv = *reinterpret_cast<const float2*>(&base[o]);
                float2 ov; ov.x = acc[i][j][0] + bv.x; ov.y = acc[i][j][1] + bv.y;
                *reinterpret_cast<float2*>(&g_qs[o]) = ov;
            }
            {
                size_t o = (size_t)(row0 + 8) * CT + col;
                float2 bv = *reinterpret_cast<const float2*>(&base[o]);
                float2 ov; ov.x = acc[i][j][2] + bv.x; ov.y = acc[i][j][3] + bv.y;
                *reinterpret_cast<float2*>(&g_qs[o]) = ov;
            }
        }
    }
}

// ---------------------------------------------------------------------------
// GEMM2 (bf16, cp.async 3-stage, split-K=32): g_grad[m,z] += dqs[m,:].W[z,:]
// Both operands k-contiguous bf16, [row][20 words] padded layout.
__global__ __launch_bounds__(256, 2) void gemm2_tc()
{
    extern __shared__ uint32_t smem[];
    uint32_t* AsU = smem;                 // 3 * 2560
    uint32_t* WsU = smem + 7680;          // 3 * 2560
    const uint32_t sA = (uint32_t)__cvta_generic_to_shared(AsU);
    const uint32_t sW = (uint32_t)__cvta_generic_to_shared(WsU);

    const int tid  = threadIdx.x;
    const int lane = tid & 31;
    const int wid  = tid >> 5;
    const int wm   = wid & 1;
    const int wn   = wid >> 1;
    const int g    = lane >> 2;
    const int tg   = lane & 3;
    const int bm   = blockIdx.y << 7;
    const int bn   = blockIdx.x << 7;
    const int k0s  = blockIdx.z * (CT / 32);   // 384 per split

    float acc[4][4][4];
#pragma unroll
    for (int i = 0; i < 4; i++)
#pragma unroll
        for (int j = 0; j < 4; j++)
#pragma unroll
            for (int c = 0; c < 4; c++) acc[i][j][c] = 0.f;

    auto loadTiles = [&](int kb, int s) {
#pragma unroll
        for (int it = 0; it < 2; it++) {
            int f = tid + it * 256;
            int m = f >> 2, cq = f & 3;
            cp16(sA + ((s * 2560 + m * 20 + cq * 4) << 2),
                 &g_dqsb[(size_t)(bm + m) * CT + kb + cq * 8]);
        }
#pragma unroll
        for (int it = 0; it < 2; it++) {
            int f = tid + it * 256;
            int z = f >> 2, cq = f & 3;
            cp16(sW + ((s * 2560 + z * 20 + cq * 4) << 2),
                 &g_W2[(size_t)(bn + z) * CT + kb + cq * 8]);
        }
    };

    loadTiles(k0s, 0);      CP_COMMIT();
    loadTiles(k0s + 32, 1); CP_COMMIT();

    const int NK = (CT / 32) / 32;  // 12
    int stage = 0;
    int lstage = 2;
    for (int kt = 0; kt < NK; kt++) {
        CP_WAIT1();
        __syncthreads();
        if (kt + 2 < NK) {
            loadTiles(k0s + (kt + 2) * 32, lstage);
            if (++lstage == 3) lstage = 0;
        }
        CP_COMMIT();

        const uint32_t* as = AsU + stage * 2560;
        const uint32_t* ws = WsU + stage * 2560;
        if (++stage == 3) stage = 0;
#pragma unroll
        for (int ks = 0; ks < 2; ks++) {
            const int kc2 = ks * 8;
            uint32_t afr[4][4];
#pragma unroll
            for (int i = 0; i < 4; i++) {
                int r0 = wm * 64 + i * 16 + g;
                afr[i][0] = as[r0 * 20 + kc2 + tg];
                afr[i][1] = as[(r0 + 8) * 20 + kc2 + tg];
                afr[i][2] = as[r0 * 20 + kc2 + tg + 4];
                afr[i][3] = as[(r0 + 8) * 20 + kc2 + tg + 4];
            }
            uint32_t bfr[4][2];
#pragma unroll
            for (int j = 0; j < 4; j++) {
                int c0 = wn * 32 + j * 8 + g;
                bfr[j][0] = ws[c0 * 20 + kc2 + tg];
                bfr[j][1] = ws[c0 * 20 + kc2 + tg + 4];
            }
#pragma unroll
            for (int i = 0; i < 4; i++)
#pragma unroll
                for (int j = 0; j < 4; j++)
                    mma_bf16(acc[i][j][0], acc[i][j][1], acc[i][j][2], acc[i][j][3],
                             afr[i][0], afr[i][1], afr[i][2], afr[i][3],
                             bfr[j][0], bfr[j][1]);
        }
    }

#pragma unroll
    for (int i = 0; i < 4; i++)
#pragma unroll
        for (int j = 0; j < 4; j++) {
            int row0 = bm + wm * 64 + i * 16 + g;
            int col  = bn + wn * 32 + j * 8 + 2 * tg;
            atomicAdd(&g_grad[(size_t)row0 * ZZ + col],           acc[i][j][0]);
            atomicAdd(&g_grad[(size_t)row0 * ZZ + col + 1],       acc[i][j][1]);
            atomicAdd(&g_grad[(size_t)(row0 + 8) * ZZ + col],     acc[i][j][2]);
            atomicAdd(&g_grad[(size_t)(row0 + 8) * ZZ + col + 1], acc[i][j][3]);
        }
}

// ---------------------------------------------------------------------------
__device__ __forceinline__ void qrot(const float* __restrict__ q,
                                     const float* __restrict__ v,
                                     float* __restrict__ r)
{
    float w = q[0], x = q[1], y = q[2], z = q[3];
    float inv = 1.0f / (w * w + x * x + y * y + z * z);
    float a = w * w - (x * x + y * y + z * z);
    float d = 2.0f * (x * v[0] + y * v[1] + z * v[2]);
    float cx = y * v[2] - z * v[1];
    float cy = z * v[0] - x * v[2];
    float cz = x * v[1] - y * v[0];
    float tw = 2.0f * w;
    r[0] = (a * v[0] + d * x + tw * cx) * inv;
    r[1] = (a * v[1] + d * y + tw * cy) * inv;
    r[2] = (a * v[2] + d * z + tw * cz) * inv;
}

__device__ __forceinline__ void qrot_bwd(const float* __restrict__ q,
                                         const float* __restrict__ v,
                                         const float* __restrict__ g,
                                         float& dw, float& dx, float& dy, float& dz)
{
    float w = q[0], x = q[1], y = q[2], z = q[3];
    float inv = 1.0f / (w * w + x * x + y * y + z * z);
    float a = w * w - (x * x + y * y + z * z);
    float dd = 2.0f * (x * v[0] + y * v[1] + z * v[2]);
    float cx = y * v[2] - z * v[1];
    float cy = z * v[0] - x * v[2];
    float cz = x * v[1] - y * v[0];
    float tw = 2.0f * w;
    float r0 = (a * v[0] + dd * x + tw * cx) * inv;
    float r1 = (a * v[1] + dd * y + tw * cy) * inv;
    float r2 = (a * v[2] + dd * z + tw * cz) * inv;
    float c1 = v[0] * g[0] + v[1] * g[1] + v[2] * g[2];
    float c2 = x * g[0] + y * g[1] + z * g[2];
    float c3 = 0.5f * dd;
    float gr = g[0] * r0 + g[1] * r1 + g[2] * r2;
    float cg = cx * g[0] + cy * g[1] + cz * g[2];
    float s = 2.0f * inv;
    float vgx = v[1] * g[2] - v[2] * g[1];
    float vgy = v[2] * g[0] - v[0] * g[2];
    float vgz = v[0] * g[1] - v[1] * g[0];
    dw += s * (w * c1 + cg - w * gr);
    dx += s * (-c1 * x + c2 * v[0] + c3 * g[0] + w * vgx - gr * x);
    dy += s * (-c1 * y + c2 * v[1] + c3 * g[1] + w * vgy - gr * y);
    dz += s * (-c1 * z + c2 * v[2] + c3 * g[2] + w * vgz - gr * z);
}

// ---------------------------------------------------------------------------
// Pose kernel, k-split (round-7 structure); dqs written as bf16.
__global__ __launch_bounds__(256) void pose_kernel(const float* __restrict__ tgt,
                                                   const float* __restrict__ stdq,
                                                   const float* __restrict__ meanq,
                                                   const float* __restrict__ offs)
{
    __shared__ float s_std[CC], s_mean[CC], s_off[JJ * 3];
    __shared__ float s_buf[72 * 128];
    __shared__ float s_red[32];
    const int b  = blockIdx.x;
    const int t  = threadIdx.x;
    const int tk = t >> 7;
    const int tt = t & 127;
    if (t < CC) { s_std[t] = stdq[t]; s_mean[t] = meanq[t]; }
    if (t >= 128 && t < 128 + JJ * 3) s_off[t - 128] = offs[b * JJ * 3 + (t - 128)];
    __syncthreads();

    float accR = 0.f, accJ = 0.f, accF = 0.f;

    const float* dbase = g_qs + (size_t)(b * 2 + tk) * CT + tt;
    const float* tbase = tgt + (size_t)(b * 2 + tk) * (2 * CT) + tt;

    {
#pragma unroll
        for (int i = 0; i < 4; i++) {
            float df = dbase[(size_t)i * TT] - tbase[(size_t)i * TT];
            accR += df * df;
        }
        const int leaves[5] = { 10, 11, 15, 22, 23 };
#pragma unroll
        for (int e = 0; e < 5; e++) {
            int j = leaves[e];
#pragma unroll
            for (int i = 0; i < 4; i++) {
                float df = dbase[(size_t)(4 * j + i) * TT] - tbase[(size_t)(8 * j + i) * TT];
                accJ += df * df;
            }
        }
    }

    float pd[72];
    {
        float qD[4], qT[4];
        float pDx, pDy, pDz, pTx, pTy, pTz;

        auto loadPair = [&](int j) {
#pragma unroll
            for (int i = 0; i < 4; i++) {
                int c = 4 * j + i;
                float d  = dbase[(size_t)c * TT];
                float tr = tbase[(size_t)(8 * j + i) * TT];
                float df = d - tr;
                accJ += df * df;
                qD[i] = d * s_std[c] + s_mean[c];
                qT[i] = tr * s_std[c] + s_mean[c];
            }
        };
        auto step = [&](int j) {
            const float* v = s_off + 3 * j;
            float r[3];
            qrot(qD, v, r); pDx += r[0]; pDy += r[1]; pDz += r[2];
            qrot(qT, v, r); pTx += r[0]; pTy += r[1]; pTz += r[2];
            float dx = pDx - pTx, dy = pDy - pTy, dz = pDz - pTz;
            accF += dx * dx + dy * dy + dz * dz;
            pd[3 * j + 0] = pDx; pd[3 * j + 1] = pDy; pd[3 * j + 2] = pDz;
        };
        auto reset = [&]() {
            pDx = pDy = pDz = pTx = pTy = pTz = 0.f;
            qD[0] = 1.f; qD[1] = qD[2] = qD[3] = 0.f;
            qT[0] = 1.f; qT[1] = qT[2] = qT[3] = 0.f;
        };

        reset();
        step(1); loadPair(1); step(4); loadPair(4); step(7); loadPair(7); step(10);
        reset();
        step(2); loadPair(2); step(5); loadPair(5); step(8); loadPair(8); step(11);
        reset();
        step(3); loadPair(3); step(6); loadPair(6); step(9); loadPair(9);
        float sp[6] = { pDx, pDy, pDz, pTx, pTy, pTz };
        float sqD[4] = { qD[0], qD[1], qD[2], qD[3] };
        float sqT[4] = { qT[0], qT[1], qT[2], qT[3] };
        step(12); loadPair(12); step(15);
        pDx = sp[0]; pDy = sp[1]; pDz = sp[2]; pTx = sp[3]; pTy = sp[4]; pTz = sp[5];
        qD[0] = sqD[0]; qD[1] = sqD[1]; qD[2] = sqD[2]; qD[3] = sqD[3];
        qT[0] = sqT[0]; qT[1] = sqT[1]; qT[2] = sqT[2]; qT[3] = sqT[3];
        step(13); loadPair(13); step(16); loadPair(16); step(18); loadPair(18);
        step(20); loadPair(20); step(22);
        pDx = sp[0]; pDy = sp[1]; pDz = sp[2]; pTx = sp[3]; pTy = sp[4]; pTz = sp[5];
        qD[0] = sqD[0]; qD[1] = sqD[1]; qD[2] = sqD[2]; qD[3] = sqD[3];
        qT[0] = sqT[0]; qT[1] = sqT[1]; qT[2] = sqT[2]; qT[3] = sqT[3];
        step(14); loadPair(14); step(17); loadPair(17); step(19); loadPair(19);
        step(21); loadPair(21); step(23);
    }

    if (tk == 1) {
#pragma unroll
        for (int r = 3; r < 72; r++) s_buf[r * 128 + tt] = pd[r];
    }
    __syncthreads();

    if (tk == 0) {
#pragma unroll
        for (int r = 3; r < 72; r++) pd[r] = 2.f * (pd[r] - s_buf[r * 128 + tt]);
        const int ch[20] = { 23,22,21,20,19,18,17,16,15,14,13,12,11,10,9,8,7,6,5,4 };
        const int pa[20] = { 21,20,19,18,17,16,14,13,12, 9, 9, 9, 8, 7, 6, 5, 4, 3, 2, 1 };
#pragma unroll
        for (int e = 0; e < 20; e++) {
            int cj = ch[e], pj = pa[e];
            pd[3 * pj + 0] += pd[3 * cj + 0];
            pd[3 * pj + 1] += pd[3 * cj + 1];
            pd[3 * pj + 2] += pd[3 * cj + 2];
        }
#pragma unroll
        for (int r = 3; r < 72; r++) s_buf[r * 128 + tt] = pd[r];
    }
    __syncthreads();
    if (tk == 1) {
#pragma unroll
        for (int r = 3; r < 72; r++) pd[r] = s_buf[r * 128 + tt];
    }

    __nv_bfloat16* outp = g_dqsb + (size_t)b * CT + tt;
    const float* dbase0 = g_qs + (size_t)(b * 2) * CT + tt;
    auto doParent = [&](int p, int c0, int c1, int c2) {
        float q[4];
#pragma unroll
        for (int i = 0; i < 4; i++) {
            int c = 4 * p + i;
            q[i] = dbase0[(size_t)c * TT] * s_std[c] + s_mean[c];
        }
        float dw = 0.f, dx = 0.f, dy = 0.f, dz = 0.f;
        qrot_bwd(q, s_off + 3 * c0, pd + 3 * c0, dw, dx, dy, dz);
        if (c1 >= 0) qrot_bwd(q, s_off + 3 * c1, pd + 3 * c1, dw, dx, dy, dz);
        if (c2 >= 0) qrot_bwd(q, s_off + 3 * c2, pd + 3 * c2, dw, dx, dy, dz);
        outp[(size_t)(4 * p + 0) * TT] = __float2bfloat16_rn(dw * s_std[4 * p + 0]);
        outp[(size_t)(4 * p + 1) * TT] = __float2bfloat16_rn(dx * s_std[4 * p + 1]);
        outp[(size_t)(4 * p + 2) * TT] = __float2bfloat16_rn(dy * s_std[4 * p + 2]);
        outp[(size_t)(4 * p + 3) * TT] = __float2bfloat16_rn(dz * s_std[4 * p + 3]);
    };
    const __nv_bfloat16 bz = __float2bfloat16_rn(0.f);
    if (tk == 0) {
        const int zj[3] = { 0, 10, 11 };
#pragma unroll
        for (int e = 0; e < 3; e++)
#pragma unroll
            for (int i = 0; i < 4; i++)
                outp[(size_t)(4 * zj[e] + i) * TT] = bz;
        doParent(1, 4, -1, -1);  doParent(2, 5, -1, -1);  doParent(3, 6, -1, -1);
        doParent(4, 7, -1, -1);  doParent(5, 8, -1, -1);  doParent(6, 9, -1, -1);
        doParent(7, 10, -1, -1); doParent(8, 11, -1, -1);
        doParent(9, 12, 13, 14);
    } else {
        const int zj[3] = { 15, 22, 23 };
#pragma unroll
        for (int e = 0; e < 3; e++)
#pragma unroll
            for (int i = 0; i < 4; i++)
                outp[(size_t)(4 * zj[e] + i) * TT] = bz;
        doParent(12, 15, -1, -1); doParent(13, 16, -1, -1); doParent(14, 17, -1, -1);
        doParent(16, 18, -1, -1); doParent(17, 19, -1, -1); doParent(18, 20, -1, -1);
        doParent(19, 21, -1, -1); doParent(20, 22, -1, -1); doParent(21, 23, -1, -1);
    }

    float r = blockReduce(accR, s_red);
    if (threadIdx.x == 0) atomicAdd(&g_acc[0], (double)r);
    __syncthreads();
    r = blockReduce(accJ, s_red);
    if (threadIdx.x == 0) atomicAdd(&g_acc[1], (double)r);
    __syncthreads();
    r = blockReduce(accF, s_red);
    if (threadIdx.x == 0) atomicAdd(&g_acc[2], (double)r);
}

// ---------------------------------------------------------------------------
// cons + disp + KLD reductions
__global__ void cons_kernel(const float* __restrict__ lat,
                            const float* __restrict__ id, const float* __restrict__ td,
                            const float* __restrict__ mu, const float* __restrict__ lv)
{
    __shared__ float s_red[32];
    int i = blockIdx.x * blockDim.x + threadIdx.x;
    int stride = gridDim.x * blockDim.x;   // 131072
    int b = i >> 8, z = i & 255;
    float d = lat[(size_t)(2 * b) * ZZ + z] - g_grad[i] - lat[(size_t)(2 * b + 1) * ZZ + z];
    float sc = d * d;
    float sd = 0.f, sk = 0.f;
    for (int k = i; k < BP * 2 * 3 * TT; k += stride) { float df = id[k] - td[k]; sd += df * df; }
    for (int k = i; k < N2 * ZZ; k += stride) {
        float m = mu[k], l = lv[k];
        sk += 1.0f + l - m * m - expf(l);
    }
    float r = blockReduce(sc, s_red);
    if (threadIdx.x == 0) atomicAdd(&g_acc[5], (double)r);
    __syncthreads();
    r = blockReduce(sd, s_red);
    if (threadIdx.x == 0) atomicAdd(&g_acc[4], (double)r);
    __syncthreads();
    r = blockReduce(sk, s_red);
    if (threadIdx.x == 0) atomicAdd(&g_acc[3], (double)r);
}

// ---------------------------------------------------------------------------
__global__ void finalize_kernel(float* out)
{
    out[0] = (float)(-0.5 * g_acc[3] / 1024.0) * 0.001f;
    out[1] = (float)(g_acc[0] / 524288.0);
    out[2] = (float)(g_acc[4] / 393216.0);
    out[3] = (float)(g_acc[5] / 131072.0) * 0.1f;
    out[4] = (float)(g_acc[2] / 9437184.0) * 0.1f;
    out[5] = (float)(g_acc[1] / 12058624.0);
}

// ---------------------------------------------------------------------------
extern "C" void kernel_launch(void* const* d_in, const int* in_sizes, int n_in,
                              void* d_out, int out_size)
{
    const float* base  = (const float*)d_in[0];
    const float* tgt   = (const float*)d_in[1];
    const float* idisp = (const float*)d_in[2];
    const float* tdisp = (const float*)d_in[3];
    const float* mu    = (const float*)d_in[4];
    const float* lv    = (const float*)d_in[5];
    const float* lat   = (const float*)d_in[6];
    const float* W     = (const float*)d_in[7];
    const float* meanq = (const float*)d_in[8];
    const float* stdq  = (const float*)d_in[9];
    const float* offs  = (const float*)d_in[10];
    float* out = (float*)d_out;

    cudaFuncSetAttribute(gemm1_tc, cudaFuncAttributeMaxDynamicSharedMemorySize, 37888);
    cudaFuncSetAttribute(gemm2_tc, cudaFuncAttributeMaxDynamicSharedMemorySize, 61440);

    zero_kernel<<<(BP * ZZ + 255) / 256, 256>>>();
    cvt_kernel<<<12800, 256>>>(W, lat);
    gemm1_tc<<<dim3(96, 8), 256, 37888>>>(base);
    pose_kernel<<<BP, 256>>>(tgt, stdq, meanq, offs);
    gemm2_tc<<<dim3(2, 4, 32), 256, 61440>>>();
    cons_kernel<<<512, 256>>>(lat, idisp, tdisp, mu, lv);
    finalize_kernel<<<1, 1>>>(out);
}

// round 10
// speedup vs baseline: 1.2682x; 1.0203x over previous
#include <cuda_runtime.h>
#include <cuda_bf16.h>
#include <cstdint>

#define BP 512
#define CC 96
#define TT 128
#define JJ 24
#define ZZ 256
#define CT 12288
#define N2 1024

__device__ float          g_qs[(size_t)N2 * CT];     // decoded motion fp32
__device__ __nv_bfloat16  g_dqsb[(size_t)BP * CT];   // d f / d qs (bf16)
__device__ float          g_grad[(size_t)BP * ZZ];   // grad wrt latent[:,0]
__device__ double         g_acc[6];                  // root joints fk kld disp cons
__device__ __nv_bfloat16  g_W2[(size_t)ZZ * CT];     // W bf16, [z][ct]
__device__ uint32_t       g_W1[(size_t)(ZZ / 2) * CT]; // W bf16 k-pair packed [k2][n]
__device__ __nv_bfloat16  g_latb[(size_t)N2 * ZZ];   // latent bf16

// ---------------------------------------------------------------------------
// bf16 conversions (W two layouts + latent) with zero-init folded in
__global__ void cvt_kernel(const float* __restrict__ W, const float* __restrict__ lat)
{
    const int NW  = (ZZ * CT) / 2;       // -> g_W2
    const int NW1 = (ZZ / 2) * CT;       // -> g_W1
    const int NL  = (N2 * ZZ) / 2;       // -> g_latb
    int i = blockIdx.x * blockDim.x + threadIdx.x;
    if (i < BP * ZZ) g_grad[i] = 0.f;
    if (i < 6)       g_acc[i] = 0.0;
    if (i < NW) {
        float2 v = reinterpret_cast<const float2*>(W)[i];
        reinterpret_cast<__nv_bfloat162*>(g_W2)[i] = __floats2bfloat162_rn(v.x, v.y);
    } else if (i < NW + NW1) {
        int j = i - NW;
        int k2 = j / CT, n = j - k2 * CT;
        float lo = W[(size_t)(2 * k2) * CT + n];
        float hi = W[(size_t)(2 * k2 + 1) * CT + n];
        __nv_bfloat162 h = __floats2bfloat162_rn(lo, hi);
        g_W1[j] = *reinterpret_cast<uint32_t*>(&h);
    } else if (i < NW + NW1 + NL) {
        int j = i - NW - NW1;
        float2 v = reinterpret_cast<const float2*>(lat)[j];
        reinterpret_cast<__nv_bfloat162*>(g_latb)[j] = __floats2bfloat162_rn(v.x, v.y);
    }
}

// ---------------------------------------------------------------------------
__device__ __forceinline__ float blockReduce(float v, float* sm) {
#pragma unroll
    for (int o = 16; o > 0; o >>= 1) v += __shfl_down_sync(0xffffffffu, v, o);
    int lane = threadIdx.x & 31, w = threadIdx.x >> 5;
    if (lane == 0) sm[w] = v;
    __syncthreads();
    v = 0.f;
    if (threadIdx.x < 32) {
        int nw = (blockDim.x + 31) >> 5;
        v = (threadIdx.x < nw) ? sm[threadIdx.x] : 0.f;
#pragma unroll
        for (int o = 16; o > 0; o >>= 1) v += __shfl_down_sync(0xffffffffu, v, o);
    }
    return v;
}

// ---------------------------------------------------------------------------
__device__ __forceinline__ void cp16(uint32_t dst, const void* src) {
    asm volatile("cp.async.ca.shared.global [%0], [%1], 16;\n" :: "r"(dst), "l"(src));
}
#define CP_COMMIT() asm volatile("cp.async.commit_group;\n")
#define CP_WAIT1()  asm volatile("cp.async.wait_group 1;\n")

__device__ __forceinline__ void mma_bf16(float& c0, float& c1, float& c2, float& c3,
                                         uint32_t a0, uint32_t a1, uint32_t a2, uint32_t a3,
                                         uint32_t b0, uint32_t b1)
{
    asm volatile("mma.sync.aligned.m16n8k16.row.col.f32.bf16.bf16.f32 "
                 "{%0,%1,%2,%3}, {%4,%5,%6,%7}, {%8,%9}, {%0,%1,%2,%3};"
                 : "+f"(c0), "+f"(c1), "+f"(c2), "+f"(c3)
                 : "r"(a0), "r"(a1), "r"(a2), "r"(a3), "r"(b0), "r"(b1));
}

// ---------------------------------------------------------------------------
// GEMM1 (bf16 m16n8k16, cp.async 2-stage): g_qs = latb(1024x256)@W1 + base
__global__ __launch_bounds__(256, 2) void gemm1_tc(const float* __restrict__ base)
{
    extern __shared__ uint32_t smem[];
    uint32_t* AsU = smem;                 // 2 * 2560
    uint32_t* BsU = smem + 5120;          // 2 * 2176
    const uint32_t sA = (uint32_t)__cvta_generic_to_shared(AsU);
    const uint32_t sB = (uint32_t)__cvta_generic_to_shared(BsU);

    const int tid  = threadIdx.x;
    const int lane = tid & 31;
    const int wid  = tid >> 5;
    const int wm   = wid & 1;
    const int wn   = wid >> 1;
    const int g    = lane >> 2;
    const int tg   = lane & 3;
    const int bm   = blockIdx.y << 7;
    const int bn   = blockIdx.x << 7;

    float acc[4][4][4];
#pragma unroll
    for (int i = 0; i < 4; i++)
#pragma unroll
        for (int j = 0; j < 4; j++)
#pragma unroll
            for (int c = 0; c < 4; c++) acc[i][j][c] = 0.f;

    auto loadTiles = [&](int kb, int s) {
#pragma unroll
        for (int it = 0; it < 2; it++) {
            int f = tid + it * 256;
            int m = f >> 2, cq = f & 3;
            cp16(sA + ((s * 2560 + m * 20 + cq * 4) << 2),
                 &g_latb[(size_t)(bm + m) * ZZ + kb + cq * 8]);
        }
        int kb2 = kb >> 1;
#pragma unroll
        for (int it = 0; it < 2; it++) {
            int f = tid + it * 256;
            int k2 = f >> 5, nq = f & 31;
            cp16(sB + ((s * 2176 + k2 * 136 + nq * 4) << 2),
                 &g_W1[(size_t)(kb2 + k2) * CT + bn + nq * 4]);
        }
    };

    loadTiles(0, 0);
    CP_COMMIT();

    const int NK = ZZ / 32;  // 8
    for (int kt = 0; kt < NK; kt++) {
        if (kt + 1 < NK) loadTiles((kt + 1) * 32, (kt + 1) & 1);
        CP_COMMIT();
        CP_WAIT1();
        __syncthreads();

        const uint32_t* as = AsU + (kt & 1) * 2560;
        const uint32_t* bs = BsU + (kt & 1) * 2176;
#pragma unroll
        for (int ks = 0; ks < 2; ks++) {
            const int kc2 = ks * 8;
            uint32_t afr[4][4];
#pragma unroll
            for (int i = 0; i < 4; i++) {
                int r0 = wm * 64 + i * 16 + g;
                afr[i][0] = as[r0 * 20 + kc2 + tg];
                afr[i][1] = as[(r0 + 8) * 20 + kc2 + tg];
                afr[i][2] = as[r0 * 20 + kc2 + tg + 4];
                afr[i][3] = as[(r0 + 8) * 20 + kc2 + tg + 4];
            }
            uint32_t bfr[4][2];
#pragma unroll
            for (int j = 0; j < 4; j++) {
                int c0 = wn * 32 + j * 8 + g;
                bfr[j][0] = bs[(kc2 + tg) * 136 + c0];
                bfr[j][1] = bs[(kc2 + tg + 4) * 136 + c0];
            }
#pragma unroll
            for (int i = 0; i < 4; i++)
#pragma unroll
                for (int j = 0; j < 4; j++)
                    mma_bf16(acc[i][j][0], acc[i][j][1], acc[i][j][2], acc[i][j][3],
                             afr[i][0], afr[i][1], afr[i][2], afr[i][3],
                             bfr[j][0], bfr[j][1]);
        }
        __syncthreads();
    }

#pragma unroll
    for (int i = 0; i < 4; i++) {
#pragma unroll
        for (int j = 0; j < 4; j++) {
            int row0 = bm + wm * 64 + i * 16 + g;
            int col  = bn + wn * 32 + j * 8 + 2 * tg;
            {
                size_t o = (size_t)row0 * CT + col;
                float2 bv = *reinterpret_cast<const float2*>(&base[o]);
                float2 ov; ov.x = acc[i][j][0] + bv.x; ov.y = acc[i][j][1] + bv.y;
                *reinterpret_cast<float2*>(&g_qs[o]) = ov;
            }
            {
                size_t o = (size_t)(row0 + 8) * CT + col;
                float2 bv = *reinterpret_cast<const float2*>(&base[o]);
                float2 ov; ov.x = acc[i][j][2] + bv.x; ov.y = acc[i][j][3] + bv.y;
                *reinterpret_cast<float2*>(&g_qs[o]) = ov;
            }
        }
    }
}

// ---------------------------------------------------------------------------
// GEMM2 (bf16, cp.async 3-stage, split-K=32): g_grad[m,z] += dqs[m,:].W[z,:]
__global__ __launch_bounds__(256, 2) void gemm2_tc()
{
    extern __shared__ uint32_t smem[];
    uint32_t* AsU = smem;                 // 3 * 2560
    uint32_t* WsU = smem + 7680;          // 3 * 2560
    const uint32_t sA = (uint32_t)__cvta_generic_to_shared(AsU);
    const uint32_t sW = (uint32_t)__cvta_generic_to_shared(WsU);

    const int tid  = threadIdx.x;
    const int lane = tid & 31;
    const int wid  = tid >> 5;
    const int wm   = wid & 1;
    const int wn   = wid >> 1;
    const int g    = lane >> 2;
    const int tg   = lane & 3;
    const int bm   = blockIdx.y << 7;
    const int bn   = blockIdx.x << 7;
    const int k0s  = blockIdx.z * (CT / 32);

    float acc[4][4][4];
#pragma unroll
    for (int i = 0; i < 4; i++)
#pragma unroll
        for (int j = 0; j < 4; j++)
#pragma unroll
            for (int c = 0; c < 4; c++) acc[i][j][c] = 0.f;

    auto loadTiles = [&](int kb, int s) {
#pragma unroll
        for (int it = 0; it < 2; it++) {
            int f = tid + it * 256;
            int m = f >> 2, cq = f & 3;
            cp16(sA + ((s * 2560 + m * 20 + cq * 4) << 2),
                 &g_dqsb[(size_t)(bm + m) * CT + kb + cq * 8]);
        }
#pragma unroll
        for (int it = 0; it < 2; it++) {
            int f = tid + it * 256;
            int z = f >> 2, cq = f & 3;
            cp16(sW + ((s * 2560 + z * 20 + cq * 4) << 2),
                 &g_W2[(size_t)(bn + z) * CT + kb + cq * 8]);
        }
    };

    loadTiles(k0s, 0);      CP_COMMIT();
    loadTiles(k0s + 32, 1); CP_COMMIT();

    const int NK = (CT / 32) / 32;  // 12
    int stage = 0;
    int lstage = 2;
    for (int kt = 0; kt < NK; kt++) {
        CP_WAIT1();
        __syncthreads();
        if (kt + 2 < NK) {
            loadTiles(k0s + (kt + 2) * 32, lstage);
            if (++lstage == 3) lstage = 0;
        }
        CP_COMMIT();

        const uint32_t* as = AsU + stage * 2560;
        const uint32_t* ws = WsU + stage * 2560;
        if (++stage == 3) stage = 0;
#pragma unroll
        for (int ks = 0; ks < 2; ks++) {
            const int kc2 = ks * 8;
            uint32_t afr[4][4];
#pragma unroll
            for (int i = 0; i < 4; i++) {
                int r0 = wm * 64 + i * 16 + g;
                afr[i][0] = as[r0 * 20 + kc2 + tg];
                afr[i][1] = as[(r0 + 8) * 20 + kc2 + tg];
                afr[i][2] = as[r0 * 20 + kc2 + tg + 4];
                afr[i][3] = as[(r0 + 8) * 20 + kc2 + tg + 4];
            }
            uint32_t bfr[4][2];
#pragma unroll
            for (int j = 0; j < 4; j++) {
                int c0 = wn * 32 + j * 8 + g;
                bfr[j][0] = ws[c0 * 20 + kc2 + tg];
                bfr[j][1] = ws[c0 * 20 + kc2 + tg + 4];
            }
#pragma unroll
            for (int i = 0; i < 4; i++)
#pragma unroll
                for (int j = 0; j < 4; j++)
                    mma_bf16(acc[i][j][0], acc[i][j][1], acc[i][j][2], acc[i][j][3],
                             afr[i][0], afr[i][1], afr[i][2], afr[i][3],
                             bfr[j][0], bfr[j][1]);
        }
    }

#pragma unroll
    for (int i = 0; i < 4; i++)
#pragma unroll
        for (int j = 0; j < 4; j++) {
            int row0 = bm + wm * 64 + i * 16 + g;
            int col  = bn + wn * 32 + j * 8 + 2 * tg;
            atomicAdd(&g_grad[(size_t)row0 * ZZ + col],           acc[i][j][0]);
            atomicAdd(&g_grad[(size_t)row0 * ZZ + col + 1],       acc[i][j][1]);
            atomicAdd(&g_grad[(size_t)(row0 + 8) * ZZ + col],     acc[i][j][2]);
            atomicAdd(&g_grad[(size_t)(row0 + 8) * ZZ + col + 1], acc[i][j][3]);
        }
}

// ---------------------------------------------------------------------------
__device__ __forceinline__ void qrot(const float* __restrict__ q,
                                     const float* __restrict__ v,
                                     float* __restrict__ r)
{
    float w = q[0], x = q[1], y = q[2], z = q[3];
    float inv = 1.0f / (w * w + x * x + y * y + z * z);
    float a = w * w - (x * x + y * y + z * z);
    float d = 2.0f * (x * v[0] + y * v[1] + z * v[2]);
    float cx = y * v[2] - z * v[1];
    float cy = z * v[0] - x * v[2];
    float cz = x * v[1] - y * v[0];
    float tw = 2.0f * w;
    r[0] = (a * v[0] + d * x + tw * cx) * inv;
    r[1] = (a * v[1] + d * y + tw * cy) * inv;
    r[2] = (a * v[2] + d * z + tw * cz) * inv;
}

__device__ __forceinline__ void qrot_bwd(const float* __restrict__ q,
                                         const float* __restrict__ v,
                                         const float* __restrict__ g,
                                         float& dw, float& dx, float& dy, float& dz)
{
    float w = q[0], x = q[1], y = q[2], z = q[3];
    float inv = 1.0f / (w * w + x * x + y * y + z * z);
    float a = w * w - (x * x + y * y + z * z);
    float dd = 2.0f * (x * v[0] + y * v[1] + z * v[2]);
    float cx = y * v[2] - z * v[1];
    float cy = z * v[0] - x * v[2];
    float cz = x * v[1] - y * v[0];
    float tw = 2.0f * w;
    float r0 = (a * v[0] + dd * x + tw * cx) * inv;
    float r1 = (a * v[1] + dd * y + tw * cy) * inv;
    float r2 = (a * v[2] + dd * z + tw * cz) * inv;
    float c1 = v[0] * g[0] + v[1] * g[1] + v[2] * g[2];
    float c2 = x * g[0] + y * g[1] + z * g[2];
    float c3 = 0.5f * dd;
    float gr = g[0] * r0 + g[1] * r1 + g[2] * r2;
    float cg = cx * g[0] + cy * g[1] + cz * g[2];
    float s = 2.0f * inv;
    float vgx = v[1] * g[2] - v[2] * g[1];
    float vgy = v[2] * g[0] - v[0] * g[2];
    float vgz = v[0] * g[1] - v[1] * g[0];
    dw += s * (w * c1 + cg - w * gr);
    dx += s * (-c1 * x + c2 * v[0] + c3 * g[0] + w * vgx - gr * x);
    dy += s * (-c1 * y + c2 * v[1] + c3 * g[1] + w * vgy - gr * y);
    dz += s * (-c1 * z + c2 * v[2] + c3 * g[2] + w * vgz - gr * z);
}

// ---------------------------------------------------------------------------
// Pose kernel v3: k-split + pd in SMEM (s_pd[72][256], per-thread column).
// Drops the pd[72] register array -> ~70 regs -> 3 CTAs/SM (smem-bound).
__global__ __launch_bounds__(256) void pose_kernel(const float* __restrict__ tgt,
                                                   const float* __restrict__ stdq,
                                                   const float* __restrict__ meanq,
                                                   const float* __restrict__ offs)
{
    extern __shared__ float s_pd[];          // 72*256 floats = 73728 B
    __shared__ float s_std[CC], s_mean[CC], s_off[JJ * 3];
    __shared__ float s_red[32];
    const int b  = blockIdx.x;
    const int t  = threadIdx.x;
    const int tk = t >> 7;
    const int tt = t & 127;
    if (t < CC) { s_std[t] = stdq[t]; s_mean[t] = meanq[t]; }
    if (t >= 128 && t < 128 + JJ * 3) s_off[t - 128] = offs[b * JJ * 3 + (t - 128)];
    __syncthreads();

    float accR = 0.f, accJ = 0.f, accF = 0.f;

    const float* dbase = g_qs + (size_t)(b * 2 + tk) * CT + tt;
    const float* tbase = tgt + (size_t)(b * 2 + tk) * (2 * CT) + tt;

    {
#pragma unroll
        for (int i = 0; i < 4; i++) {
            float df = dbase[(size_t)i * TT] - tbase[(size_t)i * TT];
            accR += df * df;
        }
        const int leaves[5] = { 10, 11, 15, 22, 23 };
#pragma unroll
        for (int e = 0; e < 5; e++) {
            int j = leaves[e];
#pragma unroll
            for (int i = 0; i < 4; i++) {
                float df = dbase[(size_t)(4 * j + i) * TT] - tbase[(size_t)(8 * j + i) * TT];
                accJ += df * df;
            }
        }
    }

    // ---- FK forward (this k); decoded positions stored to s_pd column t ----
    {
        float qD[4], qT[4];
        float pDx, pDy, pDz, pTx, pTy, pTz;

        auto loadPair = [&](int j) {
#pragma unroll
            for (int i = 0; i < 4; i++) {
                int c = 4 * j + i;
                float d  = dbase[(size_t)c * TT];
                float tr = tbase[(size_t)(8 * j + i) * TT];
                float df = d - tr;
                accJ += df * df;
                qD[i] = d * s_std[c] + s_mean[c];
                qT[i] = tr * s_std[c] + s_mean[c];
            }
        };
        auto step = [&](int j) {
            const float* v = s_off + 3 * j;
            float r[3];
            qrot(qD, v, r); pDx += r[0]; pDy += r[1]; pDz += r[2];
            qrot(qT, v, r); pTx += r[0]; pTy += r[1]; pTz += r[2];
            float dx = pDx - pTx, dy = pDy - pTy, dz = pDz - pTz;
            accF += dx * dx + dy * dy + dz * dz;
            s_pd[(3 * j + 0) * 256 + t] = pDx;
            s_pd[(3 * j + 1) * 256 + t] = pDy;
            s_pd[(3 * j + 2) * 256 + t] = pDz;
        };
        auto reset = [&]() {
            pDx = pDy = pDz = pTx = pTy = pTz = 0.f;
            qD[0] = 1.f; qD[1] = qD[2] = qD[3] = 0.f;
            qT[0] = 1.f; qT[1] = qT[2] = qT[3] = 0.f;
        };

        reset();
        step(1); loadPair(1); step(4); loadPair(4); step(7); loadPair(7); step(10);
        reset();
        step(2); loadPair(2); step(5); loadPair(5); step(8); loadPair(8); step(11);
        reset();
        step(3); loadPair(3); step(6); loadPair(6); step(9); loadPair(9);
        float sp[6] = { pDx, pDy, pDz, pTx, pTy, pTz };
        float sqD[4] = { qD[0], qD[1], qD[2], qD[3] };
        float sqT[4] = { qT[0], qT[1], qT[2], qT[3] };
        step(12); loadPair(12); step(15);
        pDx = sp[0]; pDy = sp[1]; pDz = sp[2]; pTx = sp[3]; pTy = sp[4]; pTz = sp[5];
        qD[0] = sqD[0]; qD[1] = sqD[1]; qD[2] = sqD[2]; qD[3] = sqD[3];
        qT[0] = sqT[0]; qT[1] = sqT[1]; qT[2] = sqT[2]; qT[3] = sqT[3];
        step(13); loadPair(13); step(16); loadPair(16); step(18); loadPair(18);
        step(20); loadPair(20); step(22);
        pDx = sp[0]; pDy = sp[1]; pDz = sp[2]; pTx = sp[3]; pTy = sp[4]; pTz = sp[5];
        qD[0] = sqD[0]; qD[1] = sqD[1]; qD[2] = sqD[2]; qD[3] = sqD[3];
        qT[0] = sqT[0]; qT[1] = sqT[1]; qT[2] = sqT[2]; qT[3] = sqT[3];
        step(14); loadPair(14); step(17); loadPair(17); step(19); loadPair(19);
        step(21); loadPair(21); step(23);
    }
    __syncthreads();

    // ---- k=0 columns: upstream grad + adjoint accumulation in smem ----
    if (tk == 0) {
#pragma unroll
        for (int r = 3; r < 72; r++) {
            float v = s_pd[r * 256 + tt];
            s_pd[r * 256 + tt] = 2.f * (v - s_pd[r * 256 + tt + 128]);
        }
        const int ch[20] = { 23,22,21,20,19,18,17,16,15,14,13,12,11,10,9,8,7,6,5,4 };
        const int pa[20] = { 21,20,19,18,17,16,14,13,12, 9, 9, 9, 8, 7, 6, 5, 4, 3, 2, 1 };
#pragma unroll
        for (int e = 0; e < 20; e++) {
            int cj = ch[e], pj = pa[e];
#pragma unroll
            for (int i = 0; i < 3; i++)
                s_pd[(3 * pj + i) * 256 + tt] += s_pd[(3 * cj + i) * 256 + tt];
        }
    }
    __syncthreads();

    // ---- backward -> g_dqsb (split across halves; grads read from column tt) ----
    __nv_bfloat16* outp = g_dqsb + (size_t)b * CT + tt;
    const float* dbase0 = g_qs + (size_t)(b * 2) * CT + tt;
    auto doParent = [&](int p, int c0, int c1, int c2) {
        float q[4];
#pragma unroll
        for (int i = 0; i < 4; i++) {
            int c = 4 * p + i;
            q[i] = dbase0[(size_t)c * TT] * s_std[c] + s_mean[c];
        }
        float dw = 0.f, dx = 0.f, dy = 0.f, dz = 0.f;
        float gv[3];
        gv[0] = s_pd[(3 * c0 + 0) * 256 + tt];
        gv[1] = s_pd[(3 * c0 + 1) * 256 + tt];
        gv[2] = s_pd[(3 * c0 + 2) * 256 + tt];
        qrot_bwd(q, s_off + 3 * c0, gv, dw, dx, dy, dz);
        if (c1 >= 0) {
            gv[0] = s_pd[(3 * c1 + 0) * 256 + tt];
            gv[1] = s_pd[(3 * c1 + 1) * 256 + tt];
            gv[2] = s_pd[(3 * c1 + 2) * 256 + tt];
            qrot_bwd(q, s_off + 3 * c1, gv, dw, dx, dy, dz);
        }
        if (c2 >= 0) {
            gv[0] = s_pd[(3 * c2 + 0) * 256 + tt];
            gv[1] = s_pd[(3 * c2 + 1) * 256 + tt];
            gv[2] = s_pd[(3 * c2 + 2) * 256 + tt];
            qrot_bwd(q, s_off + 3 * c2, gv, dw, dx, dy, dz);
        }
        outp[(size_t)(4 * p + 0) * TT] = __float2bfloat16_rn(dw * s_std[4 * p + 0]);
        outp[(size_t)(4 * p + 1) * TT] = __float2bfloat16_rn(dx * s_std[4 * p + 1]);
        outp[(size_t)(4 * p + 2) * TT] = __float2bfloat16_rn(dy * s_std[4 * p + 2]);
        outp[(size_t)(4 * p + 3) * TT] = __float2bfloat16_rn(dz * s_std[4 * p + 3]);
    };
    const __nv_bfloat16 bz = __float2bfloat16_rn(0.f);
    if (tk == 0) {
        const int zj[3] = { 0, 10, 11 };
#pragma unroll
        for (int e = 0; e < 3; e++)
#pragma unroll
            for (int i = 0; i < 4; i++)
                outp[(size_t)(4 * zj[e] + i) * TT] = bz;
        doParent(1, 4, -1, -1);  doParent(2, 5, -1, -1);  doParent(3, 6, -1, -1);
        doParent(4, 7, -1, -1);  doParent(5, 8, -1, -1);  doParent(6, 9, -1, -1);
        doParent(7, 10, -1, -1); doParent(8, 11, -1, -1);
        doParent(9, 12, 13, 14);
    } else {
        const int zj[3] = { 15, 22, 23 };
#pragma unroll
        for (int e = 0; e < 3; e++)
#pragma unroll
            for (int i = 0; i < 4; i++)
                outp[(size_t)(4 * zj[e] + i) * TT] = bz;
        doParent(12, 15, -1, -1); doParent(13, 16, -1, -1); doParent(14, 17, -1, -1);
        doParent(16, 18, -1, -1); doParent(17, 19, -1, -1); doParent(18, 20, -1, -1);
        doParent(19, 21, -1, -1); doParent(20, 22, -1, -1); doParent(21, 23, -1, -1);
    }

    float r = blockReduce(accR, s_red);
    if (threadIdx.x == 0) atomicAdd(&g_acc[0], (double)r);
    __syncthreads();
    r = blockReduce(accJ, s_red);
    if (threadIdx.x == 0) atomicAdd(&g_acc[1], (double)r);
    __syncthreads();
    r = blockReduce(accF, s_red);
    if (threadIdx.x == 0) atomicAdd(&g_acc[2], (double)r);
}

// ---------------------------------------------------------------------------
// cons + disp + KLD reductions
__global__ void cons_kernel(const float* __restrict__ lat,
                            const float* __restrict__ id, const float* __restrict__ td,
                            const float* __restrict__ mu, const float* __restrict__ lv)
{
    __shared__ float s_red[32];
    int i = blockIdx.x * blockDim.x + threadIdx.x;
    int stride = gridDim.x * blockDim.x;   // 131072
    int b = i >> 8, z = i & 255;
    float d = lat[(size_t)(2 * b) * ZZ + z] - g_grad[i] - lat[(size_t)(2 * b + 1) * ZZ + z];
    float sc = d * d;
    float sd = 0.f, sk = 0.f;
    for (int k = i; k < BP * 2 * 3 * TT; k += stride) { float df = id[k] - td[k]; sd += df * df; }
    for (int k = i; k < N2 * ZZ; k += stride) {
        float m = mu[k], l = lv[k];
        sk += 1.0f + l - m * m - expf(l);
    }
    float r = blockReduce(sc, s_red);
    if (threadIdx.x == 0) atomicAdd(&g_acc[5], (double)r);
    __syncthreads();
    r = blockReduce(sd, s_red);
    if (threadIdx.x == 0) atomicAdd(&g_acc[4], (double)r);
    __syncthreads();
    r = blockReduce(sk, s_red);
    if (threadIdx.x == 0) atomicAdd(&g_acc[3], (double)r);
}

// ---------------------------------------------------------------------------
__global__ void finalize_kernel(float* out)
{
    out[0] = (float)(-0.5 * g_acc[3] / 1024.0) * 0.001f;
    out[1] = (float)(g_acc[0] / 524288.0);
    out[2] = (float)(g_acc[4] / 393216.0);
    out[3] = (float)(g_acc[5] / 131072.0) * 0.1f;
    out[4] = (float)(g_acc[2] / 9437184.0) * 0.1f;
    out[5] = (float)(g_acc[1] / 12058624.0);
}

// ---------------------------------------------------------------------------
extern "C" void kernel_launch(void* const* d_in, const int* in_sizes, int n_in,
                              void* d_out, int out_size)
{
    const float* base  = (const float*)d_in[0];
    const float* tgt   = (const float*)d_in[1];
    const float* idisp = (const float*)d_in[2];
    const float* tdisp = (const float*)d_in[3];
    const float* mu    = (const float*)d_in[4];
    const float* lv    = (const float*)d_in[5];
    const float* lat   = (const float*)d_in[6];
    const float* W     = (const float*)d_in[7];
    const float* meanq = (const float*)d_in[8];
    const float* stdq  = (const float*)d_in[9];
    const float* offs  = (const float*)d_in[10];
    float* out = (float*)d_out;

    cudaFuncSetAttribute(gemm1_tc, cudaFuncAttributeMaxDynamicSharedMemorySize, 37888);
    cudaFuncSetAttribute(gemm2_tc, cudaFuncAttributeMaxDynamicSharedMemorySize, 61440);
    cudaFuncSetAttribute(pose_kernel, cudaFuncAttributeMaxDynamicSharedMemorySize, 73728);

    cvt_kernel<<<12800, 256>>>(W, lat);
    gemm1_tc<<<dim3(96, 8), 256, 37888>>>(base);
    pose_kernel<<<BP, 256, 73728>>>(tgt, stdq, meanq, offs);
    gemm2_tc<<<dim3(2, 4, 32), 256, 61440>>>();
    cons_kernel<<<512, 256>>>(lat, idisp, tdisp, mu, lv);
    finalize_kernel<<<1, 1>>>(out);
}

// round 11
// speedup vs baseline: 1.2717x; 1.0027x over previous
#include <cuda_runtime.h>
#include <cuda_bf16.h>
#include <cstdint>

#define BP 512
#define CC 96
#define TT 128
#define JJ 24
#define ZZ 256
#define CT 12288
#define N2 1024

__device__ float          g_qs[(size_t)N2 * CT];     // decoded motion fp32
__device__ __nv_bfloat16  g_dqsb[(size_t)BP * CT];   // d f / d qs (bf16)
__device__ float          g_grad[(size_t)BP * ZZ];   // grad wrt latent[:,0]
__device__ double         g_acc[6];                  // root joints fk kld disp cons
__device__ __nv_bfloat16  g_W2[(size_t)ZZ * CT];     // W bf16, [z][ct]
__device__ uint32_t       g_W1[(size_t)(ZZ / 2) * CT]; // W bf16 k-pair packed [k2][n]
__device__ __nv_bfloat16  g_latb[(size_t)N2 * ZZ];   // latent bf16

// ---------------------------------------------------------------------------
// bf16 conversions (W two layouts + latent) with zero-init folded in
__global__ void cvt_kernel(const float* __restrict__ W, const float* __restrict__ lat)
{
    const int NW  = (ZZ * CT) / 2;
    const int NW1 = (ZZ / 2) * CT;
    const int NL  = (N2 * ZZ) / 2;
    int i = blockIdx.x * blockDim.x + threadIdx.x;
    if (i < BP * ZZ) g_grad[i] = 0.f;
    if (i < 6)       g_acc[i] = 0.0;
    if (i < NW) {
        float2 v = reinterpret_cast<const float2*>(W)[i];
        reinterpret_cast<__nv_bfloat162*>(g_W2)[i] = __floats2bfloat162_rn(v.x, v.y);
    } else if (i < NW + NW1) {
        int j = i - NW;
        int k2 = j / CT, n = j - k2 * CT;
        float lo = W[(size_t)(2 * k2) * CT + n];
        float hi = W[(size_t)(2 * k2 + 1) * CT + n];
        __nv_bfloat162 h = __floats2bfloat162_rn(lo, hi);
        g_W1[j] = *reinterpret_cast<uint32_t*>(&h);
    } else if (i < NW + NW1 + NL) {
        int j = i - NW - NW1;
        float2 v = reinterpret_cast<const float2*>(lat)[j];
        reinterpret_cast<__nv_bfloat162*>(g_latb)[j] = __floats2bfloat162_rn(v.x, v.y);
    }
}

// ---------------------------------------------------------------------------
__device__ __forceinline__ float blockReduce(float v, float* sm) {
#pragma unroll
    for (int o = 16; o > 0; o >>= 1) v += __shfl_down_sync(0xffffffffu, v, o);
    int lane = threadIdx.x & 31, w = threadIdx.x >> 5;
    if (lane == 0) sm[w] = v;
    __syncthreads();
    v = 0.f;
    if (threadIdx.x < 32) {
        int nw = (blockDim.x + 31) >> 5;
        v = (threadIdx.x < nw) ? sm[threadIdx.x] : 0.f;
#pragma unroll
        for (int o = 16; o > 0; o >>= 1) v += __shfl_down_sync(0xffffffffu, v, o);
    }
    return v;
}

// ---------------------------------------------------------------------------
__device__ __forceinline__ void cp16(uint32_t dst, const void* src) {
    asm volatile("cp.async.ca.shared.global [%0], [%1], 16;\n" :: "r"(dst), "l"(src));
}
#define CP_COMMIT() asm volatile("cp.async.commit_group;\n")
#define CP_WAIT1()  asm volatile("cp.async.wait_group 1;\n")

__device__ __forceinline__ void mma_bf16(float& c0, float& c1, float& c2, float& c3,
                                         uint32_t a0, uint32_t a1, uint32_t a2, uint32_t a3,
                                         uint32_t b0, uint32_t b1)
{
    asm volatile("mma.sync.aligned.m16n8k16.row.col.f32.bf16.bf16.f32 "
                 "{%0,%1,%2,%3}, {%4,%5,%6,%7}, {%8,%9}, {%0,%1,%2,%3};"
                 : "+f"(c0), "+f"(c1), "+f"(c2), "+f"(c3)
                 : "r"(a0), "r"(a1), "r"(a2), "r"(a3), "r"(b0), "r"(b1));
}

__device__ __forceinline__ void ldsm_x4(uint32_t* r, uint32_t addr) {
    asm volatile("ldmatrix.sync.aligned.m8n8.x4.shared.b16 {%0,%1,%2,%3}, [%4];"
                 : "=r"(r[0]), "=r"(r[1]), "=r"(r[2]), "=r"(r[3]) : "r"(addr));
}
__device__ __forceinline__ void ldsm_x2(uint32_t* r, uint32_t addr) {
    asm volatile("ldmatrix.sync.aligned.m8n8.x2.shared.b16 {%0,%1}, [%2];"
                 : "=r"(r[0]), "=r"(r[1]) : "r"(addr));
}

// ---------------------------------------------------------------------------
// GEMM1 (bf16 m16n8k16, cp.async 2-stage, A-frags via ldmatrix):
// g_qs = latb(1024x256)@W1 + base. As: [m][20 words]; Bs: [k2][136].
__global__ __launch_bounds__(256, 2) void gemm1_tc(const float* __restrict__ base)
{
    extern __shared__ uint32_t smem[];
    uint32_t* AsU = smem;                 // 2 * 2560
    uint32_t* BsU = smem + 5120;          // 2 * 2176
    const uint32_t sA = (uint32_t)__cvta_generic_to_shared(AsU);
    const uint32_t sB = (uint32_t)__cvta_generic_to_shared(BsU);

    const int tid  = threadIdx.x;
    const int lane = tid & 31;
    const int wid  = tid >> 5;
    const int wm   = wid & 1;
    const int wn   = wid >> 1;
    const int g    = lane >> 2;
    const int tg   = lane & 3;
    const int bm   = blockIdx.y << 7;
    const int bn   = blockIdx.x << 7;

    // per-lane ldmatrix address components (A side)
    const int lr       = lane & 7;
    const int rowShift = ((lane >> 3) & 1) << 3;   // 0 or 8
    const int kShift   = (lane >> 4) << 2;         // 0 or 4 words

    float acc[4][4][4];
#pragma unroll
    for (int i = 0; i < 4; i++)
#pragma unroll
        for (int j = 0; j < 4; j++)
#pragma unroll
            for (int c = 0; c < 4; c++) acc[i][j][c] = 0.f;

    auto loadTiles = [&](int kb, int s) {
#pragma unroll
        for (int it = 0; it < 2; it++) {
            int f = tid + it * 256;
            int m = f >> 2, cq = f & 3;
            cp16(sA + ((s * 2560 + m * 20 + cq * 4) << 2),
                 &g_latb[(size_t)(bm + m) * ZZ + kb + cq * 8]);
        }
        int kb2 = kb >> 1;
#pragma unroll
        for (int it = 0; it < 2; it++) {
            int f = tid + it * 256;
            int k2 = f >> 5, nq = f & 31;
            cp16(sB + ((s * 2176 + k2 * 136 + nq * 4) << 2),
                 &g_W1[(size_t)(kb2 + k2) * CT + bn + nq * 4]);
        }
    };

    loadTiles(0, 0);
    CP_COMMIT();

    const int NK = ZZ / 32;  // 8
    for (int kt = 0; kt < NK; kt++) {
        if (kt + 1 < NK) loadTiles((kt + 1) * 32, (kt + 1) & 1);
        CP_COMMIT();
        CP_WAIT1();
        __syncthreads();

        const uint32_t aStage = (kt & 1) * 2560;
        const uint32_t* bs = BsU + (kt & 1) * 2176;
#pragma unroll
        for (int ks = 0; ks < 2; ks++) {
            const int kc2 = ks * 8;
            uint32_t afr[4][4];
#pragma unroll
            for (int i = 0; i < 4; i++) {
                int r0b = wm * 64 + i * 16;
                uint32_t aw = aStage + (uint32_t)(r0b + lr + rowShift) * 20 + kc2 + kShift;
                ldsm_x4(afr[i], sA + (aw << 2));
            }
            uint32_t bfr[4][2];
#pragma unroll
            for (int j = 0; j < 4; j++) {
                int c0 = wn * 32 + j * 8 + g;
                bfr[j][0] = bs[(kc2 + tg) * 136 + c0];
                bfr[j][1] = bs[(kc2 + tg + 4) * 136 + c0];
            }
#pragma unroll
            for (int i = 0; i < 4; i++)
#pragma unroll
                for (int j = 0; j < 4; j++)
                    mma_bf16(acc[i][j][0], acc[i][j][1], acc[i][j][2], acc[i][j][3],
                             afr[i][0], afr[i][1], afr[i][2], afr[i][3],
                             bfr[j][0], bfr[j][1]);
        }
        __syncthreads();
    }

#pragma unroll
    for (int i = 0; i < 4; i++) {
#pragma unroll
        for (int j = 0; j < 4; j++) {
            int row0 = bm + wm * 64 + i * 16 + g;
            int col  = bn + wn * 32 + j * 8 + 2 * tg;
            {
                size_t o = (size_t)row0 * CT + col;
                float2 bv = *reinterpret_cast<const float2*>(&base[o]);
                float2 ov; ov.x = acc[i][j][0] + bv.x; ov.y = acc[i][j][1] + bv.y;
                *reinterpret_cast<float2*>(&g_qs[o]) = ov;
            }
            {
                size_t o = (size_t)(row0 + 8) * CT + col;
                float2 bv = *reinterpret_cast<const float2*>(&base[o]);
                float2 ov; ov.x = acc[i][j][2] + bv.x; ov.y = acc[i][j][3] + bv.y;
                *reinterpret_cast<float2*>(&g_qs[o]) = ov;
            }
        }
    }
}

// ---------------------------------------------------------------------------
// GEMM2 (bf16, cp.async 3-stage, split-K=32, full ldmatrix fragments)
__global__ __launch_bounds__(256, 2) void gemm2_tc()
{
    extern __shared__ uint32_t smem[];
    uint32_t* AsU = smem;                 // 3 * 2560
    uint32_t* WsU = smem + 7680;          // 3 * 2560
    const uint32_t sA = (uint32_t)__cvta_generic_to_shared(AsU);
    const uint32_t sW = (uint32_t)__cvta_generic_to_shared(WsU);

    const int tid  = threadIdx.x;
    const int lane = tid & 31;
    const int wid  = tid >> 5;
    const int wm   = wid & 1;
    const int wn   = wid >> 1;
    const int bm   = blockIdx.y << 7;
    const int bn   = blockIdx.x << 7;
    const int k0s  = blockIdx.z * (CT / 32);

    const int lr       = lane & 7;
    const int rowShift = ((lane >> 3) & 1) << 3;
    const int kShift   = (lane >> 4) << 2;
    const int selB     = ((lane >> 3) & 1) << 2;   // words: 0 or 4

    float acc[4][4][4];
#pragma unroll
    for (int i = 0; i < 4; i++)
#pragma unroll
        for (int j = 0; j < 4; j++)
#pragma unroll
            for (int c = 0; c < 4; c++) acc[i][j][c] = 0.f;

    auto loadTiles = [&](int kb, int s) {
#pragma unroll
        for (int it = 0; it < 2; it++) {
            int f = tid + it * 256;
            int m = f >> 2, cq = f & 3;
            cp16(sA + ((s * 2560 + m * 20 + cq * 4) << 2),
                 &g_dqsb[(size_t)(bm + m) * CT + kb + cq * 8]);
        }
#pragma unroll
        for (int it = 0; it < 2; it++) {
            int f = tid + it * 256;
            int z = f >> 2, cq = f & 3;
            cp16(sW + ((s * 2560 + z * 20 + cq * 4) << 2),
                 &g_W2[(size_t)(bn + z) * CT + kb + cq * 8]);
        }
    };

    loadTiles(k0s, 0);      CP_COMMIT();
    loadTiles(k0s + 32, 1); CP_COMMIT();

    const int NK = (CT / 32) / 32;  // 12
    int stage = 0;
    int lstage = 2;
    for (int kt = 0; kt < NK; kt++) {
        CP_WAIT1();
        __syncthreads();
        if (kt + 2 < NK) {
            loadTiles(k0s + (kt + 2) * 32, lstage);
            if (++lstage == 3) lstage = 0;
        }
        CP_COMMIT();

        const uint32_t base = stage * 2560;
        if (++stage == 3) stage = 0;
#pragma unroll
        for (int ks = 0; ks < 2; ks++) {
            const int kc2 = ks * 8;
            uint32_t afr[4][4];
#pragma unroll
            for (int i = 0; i < 4; i++) {
                int r0b = wm * 64 + i * 16;
                uint32_t aw = base + (uint32_t)(r0b + lr + rowShift) * 20 + kc2 + kShift;
                ldsm_x4(afr[i], sA + (aw << 2));
            }
            uint32_t bfr[4][2];
#pragma unroll
            for (int j = 0; j < 4; j++) {
                int c0b = wn * 32 + j * 8;
                uint32_t bw = base + (uint32_t)(c0b + lr) * 20 + kc2 + selB;
                ldsm_x2(bfr[j], sW + (bw << 2));
            }
#pragma unroll
            for (int i = 0; i < 4; i++)
#pragma unroll
                for (int j = 0; j < 4; j++)
                    mma_bf16(acc[i][j][0], acc[i][j][1], acc[i][j][2], acc[i][j][3],
                             afr[i][0], afr[i][1], afr[i][2], afr[i][3],
                             bfr[j][0], bfr[j][1]);
        }
    }

    const int g  = lane >> 2;
    const int tg = lane & 3;
#pragma unroll
    for (int i = 0; i < 4; i++)
#pragma unroll
        for (int j = 0; j < 4; j++) {
            int row0 = bm + wm * 64 + i * 16 + g;
            int col  = bn + wn * 32 + j * 8 + 2 * tg;
            atomicAdd(&g_grad[(size_t)row0 * ZZ + col],           acc[i][j][0]);
            atomicAdd(&g_grad[(size_t)row0 * ZZ + col + 1],       acc[i][j][1]);
            atomicAdd(&g_grad[(size_t)(row0 + 8) * ZZ + col],     acc[i][j][2]);
            atomicAdd(&g_grad[(size_t)(row0 + 8) * ZZ + col + 1], acc[i][j][3]);
        }
}

// ---------------------------------------------------------------------------
__device__ __forceinline__ void qrot(const float* __restrict__ q,
                                     const float* __restrict__ v,
                                     float* __restrict__ r)
{
    float w = q[0], x = q[1], y = q[2], z = q[3];
    float inv = 1.0f / (w * w + x * x + y * y + z * z);
    float a = w * w - (x * x + y * y + z * z);
    float d = 2.0f * (x * v[0] + y * v[1] + z * v[2]);
    float cx = y * v[2] - z * v[1];
    float cy = z * v[0] - x * v[2];
    float cz = x * v[1] - y * v[0];
    float tw = 2.0f * w;
    r[0] = (a * v[0] + d * x + tw * cx) * inv;
    r[1] = (a * v[1] + d * y + tw * cy) * inv;
    r[2] = (a * v[2] + d * z + tw * cz) * inv;
}

__device__ __forceinline__ void qrot_bwd(const float* __restrict__ q,
                                         const float* __restrict__ v,
                                         const float* __restrict__ g,
                                         float& dw, float& dx, float& dy, float& dz)
{
    float w = q[0], x = q[1], y = q[2], z = q[3];
    float inv = 1.0f / (w * w + x * x + y * y + z * z);
    float a = w * w - (x * x + y * y + z * z);
    float dd = 2.0f * (x * v[0] + y * v[1] + z * v[2]);
    float cx = y * v[2] - z * v[1];
    float cy = z * v[0] - x * v[2];
    float cz = x * v[1] - y * v[0];
    float tw = 2.0f * w;
    float r0 = (a * v[0] + dd * x + tw * cx) * inv;
    float r1 = (a * v[1] + dd * y + tw * cy) * inv;
    float r2 = (a * v[2] + dd * z + tw * cz) * inv;
    float c1 = v[0] * g[0] + v[1] * g[1] + v[2] * g[2];
    float c2 = x * g[0] + y * g[1] + z * g[2];
    float c3 = 0.5f * dd;
    float gr = g[0] * r0 + g[1] * r1 + g[2] * r2;
    float cg = cx * g[0] + cy * g[1] + cz * g[2];
    float s = 2.0f * inv;
    float vgx = v[1] * g[2] - v[2] * g[1];
    float vgy = v[2] * g[0] - v[0] * g[2];
    float vgz = v[0] * g[1] - v[1] * g[0];
    dw += s * (w * c1 + cg - w * gr);
    dx += s * (-c1 * x + c2 * v[0] + c3 * g[0] + w * vgx - gr * x);
    dy += s * (-c1 * y + c2 * v[1] + c3 * g[1] + w * vgy - gr * y);
    dz += s * (-c1 * z + c2 * v[2] + c3 * g[2] + w * vgz - gr * z);
}

// ---------------------------------------------------------------------------
// Pose kernel: k-split, pd in SMEM (69 rows x 256), 3 CTAs/SM target.
#define SPD(r) s_pd[((r) - 3) * 256]
__global__ __launch_bounds__(256, 3) void pose_kernel(const float* __restrict__ tgt,
                                                      const float* __restrict__ stdq,
                                                      const float* __restrict__ meanq,
                                                      const float* __restrict__ offs)
{
    extern __shared__ float s_pd[];          // 69*256 floats = 70656 B
    __shared__ float s_std[CC], s_mean[CC], s_off[JJ * 3];
    __shared__ float s_red[32];
    const int b  = blockIdx.x;
    const int t  = threadIdx.x;
    const int tk = t >> 7;
    const int tt = t & 127;
    if (t < CC) { s_std[t] = stdq[t]; s_mean[t] = meanq[t]; }
    if (t >= 128 && t < 128 + JJ * 3) s_off[t - 128] = offs[b * JJ * 3 + (t - 128)];
    __syncthreads();

    float accR = 0.f, accJ = 0.f, accF = 0.f;

    const float* dbase = g_qs + (size_t)(b * 2 + tk) * CT + tt;
    const float* tbase = tgt + (size_t)(b * 2 + tk) * (2 * CT) + tt;

    {
#pragma unroll
        for (int i = 0; i < 4; i++) {
            float df = dbase[(size_t)i * TT] - tbase[(size_t)i * TT];
            accR += df * df;
        }
        const int leaves[5] = { 10, 11, 15, 22, 23 };
#pragma unroll
        for (int e = 0; e < 5; e++) {
            int j = leaves[e];
#pragma unroll
            for (int i = 0; i < 4; i++) {
                float df = dbase[(size_t)(4 * j + i) * TT] - tbase[(size_t)(8 * j + i) * TT];
                accJ += df * df;
            }
        }
    }

    // ---- FK forward (this k); decoded positions stored to SPD column t ----
    {
        float qD[4], qT[4];
        float pDx, pDy, pDz, pTx, pTy, pTz;

        auto loadPair = [&](int j) {
#pragma unroll
            for (int i = 0; i < 4; i++) {
                int c = 4 * j + i;
                float d  = dbase[(size_t)c * TT];
                float tr = tbase[(size_t)(8 * j + i) * TT];
                float df = d - tr;
                accJ += df * df;
                qD[i] = d * s_std[c] + s_mean[c];
                qT[i] = tr * s_std[c] + s_mean[c];
            }
        };
        auto step = [&](int j) {
            const float* v = s_off + 3 * j;
            float r[3];
            qrot(qD, v, r); pDx += r[0]; pDy += r[1]; pDz += r[2];
            qrot(qT, v, r); pTx += r[0]; pTy += r[1]; pTz += r[2];
            float dx = pDx - pTx, dy = pDy - pTy, dz = pDz - pTz;
            accF += dx * dx + dy * dy + dz * dz;
            (&SPD(3 * j + 0))[t] = pDx;
            (&SPD(3 * j + 1))[t] = pDy;
            (&SPD(3 * j + 2))[t] = pDz;
        };
        auto reset = [&]() {
            pDx = pDy = pDz = pTx = pTy = pTz = 0.f;
            qD[0] = 1.f; qD[1] = qD[2] = qD[3] = 0.f;
            qT[0] = 1.f; qT[1] = qT[2] = qT[3] = 0.f;
        };

        reset();
        step(1); loadPair(1); step(4); loadPair(4); step(7); loadPair(7); step(10);
        reset();
        step(2); loadPair(2); step(5); loadPair(5); step(8); loadPair(8); step(11);
        reset();
        step(3); loadPair(3); step(6); loadPair(6); step(9); loadPair(9);
        float sp[6] = { pDx, pDy, pDz, pTx, pTy, pTz };
        float sqD[4] = { qD[0], qD[1], qD[2], qD[3] };
        float sqT[4] = { qT[0], qT[1], qT[2], qT[3] };
        step(12); loadPair(12); step(15);
        pDx = sp[0]; pDy = sp[1]; pDz = sp[2]; pTx = sp[3]; pTy = sp[4]; pTz = sp[5];
        qD[0] = sqD[0]; qD[1] = sqD[1]; qD[2] = sqD[2]; qD[3] = sqD[3];
        qT[0] = sqT[0]; qT[1] = sqT[1]; qT[2] = sqT[2]; qT[3] = sqT[3];
        step(13); loadPair(13); step(16); loadPair(16); step(18); loadPair(18);
        step(20); loadPair(20); step(22);
        pDx = sp[0]; pDy = sp[1]; pDz = sp[2]; pTx = sp[3]; pTy = sp[4]; pTz = sp[5];
        qD[0] = sqD[0]; qD[1] = sqD[1]; qD[2] = sqD[2]; qD[3] = sqD[3];
        qT[0] = sqT[0]; qT[1] = sqT[1]; qT[2] = sqT[2]; qT[3] = sqT[3];
        step(14); loadPair(14); step(17); loadPair(17); step(19); loadPair(19);
        step(21); loadPair(21); step(23);
    }
    __syncthreads();

    // ---- k=0 columns: upstream grad + adjoint accumulation in smem ----
    if (tk == 0) {
#pragma unroll
        for (int r = 3; r < 72; r++) {
            float* row = &SPD(r);
            float v = row[tt];
            row[tt] = 2.f * (v - row[tt + 128]);
        }
        const int ch[20] = { 23,22,21,20,19,18,17,16,15,14,13,12,11,10,9,8,7,6,5,4 };
        const int pa[20] = { 21,20,19,18,17,16,14,13,12, 9, 9, 9, 8, 7, 6, 5, 4, 3, 2, 1 };
#pragma unroll
        for (int e = 0; e < 20; e++) {
            int cj = ch[e], pj = pa[e];
#pragma unroll
            for (int i = 0; i < 3; i++)
                (&SPD(3 * pj + i))[tt] += (&SPD(3 * cj + i))[tt];
        }
    }
    __syncthreads();

    // ---- backward -> g_dqsb (split across halves) ----
    __nv_bfloat16* outp = g_dqsb + (size_t)b * CT + tt;
    const float* dbase0 = g_qs + (size_t)(b * 2) * CT + tt;
    auto doParent = [&](int p, int c0, int c1, int c2) {
        float q[4];
#pragma unroll
        for (int i = 0; i < 4; i++) {
            int c = 4 * p + i;
            q[i] = dbase0[(size_t)c * TT] * s_std[c] + s_mean[c];
        }
        float dw = 0.f, dx = 0.f, dy = 0.f, dz = 0.f;
        float gv[3];
        gv[0] = (&SPD(3 * c0 + 0))[tt];
        gv[1] = (&SPD(3 * c0 + 1))[tt];
        gv[2] = (&SPD(3 * c0 + 2))[tt];
        qrot_bwd(q, s_off + 3 * c0, gv, dw, dx, dy, dz);
        if (c1 >= 0) {
            gv[0] = (&SPD(3 * c1 + 0))[tt];
            gv[1] = (&SPD(3 * c1 + 1))[tt];
            gv[2] = (&SPD(3 * c1 + 2))[tt];
            qrot_bwd(q, s_off + 3 * c1, gv, dw, dx, dy, dz);
        }
        if (c2 >= 0) {
            gv[0] = (&SPD(3 * c2 + 0))[tt];
            gv[1] = (&SPD(3 * c2 + 1))[tt];
            gv[2] = (&SPD(3 * c2 + 2))[tt];
            qrot_bwd(q, s_off + 3 * c2, gv, dw, dx, dy, dz);
        }
        outp[(size_t)(4 * p + 0) * TT] = __float2bfloat16_rn(dw * s_std[4 * p + 0]);
        outp[(size_t)(4 * p + 1) * TT] = __float2bfloat16_rn(dx * s_std[4 * p + 1]);
        outp[(size_t)(4 * p + 2) * TT] = __float2bfloat16_rn(dy * s_std[4 * p + 2]);
        outp[(size_t)(4 * p + 3) * TT] = __float2bfloat16_rn(dz * s_std[4 * p + 3]);
    };
    const __nv_bfloat16 bz = __float2bfloat16_rn(0.f);
    if (tk == 0) {
        const int zj[3] = { 0, 10, 11 };
#pragma unroll
        for (int e = 0; e < 3; e++)
#pragma unroll
            for (int i = 0; i < 4; i++)
                outp[(size_t)(4 * zj[e] + i) * TT] = bz;
        doParent(1, 4, -1, -1);  doParent(2, 5, -1, -1);  doParent(3, 6, -1, -1);
        doParent(4, 7, -1, -1);  doParent(5, 8, -1, -1);  doParent(6, 9, -1, -1);
        doParent(7, 10, -1, -1); doParent(8, 11, -1, -1);
        doParent(9, 12, 13, 14);
    } else {
        const int zj[3] = { 15, 22, 23 };
#pragma unroll
        for (int e = 0; e < 3; e++)
#pragma unroll
            for (int i = 0; i < 4; i++)
                outp[(size_t)(4 * zj[e] + i) * TT] = bz;
        doParent(12, 15, -1, -1); doParent(13, 16, -1, -1); doParent(14, 17, -1, -1);
        doParent(16, 18, -1, -1); doParent(17, 19, -1, -1); doParent(18, 20, -1, -1);
        doParent(19, 21, -1, -1); doParent(20, 22, -1, -1); doParent(21, 23, -1, -1);
    }

    float r = blockReduce(accR, s_red);
    if (threadIdx.x == 0) atomicAdd(&g_acc[0], (double)r);
    __syncthreads();
    r = blockReduce(accJ, s_red);
    if (threadIdx.x == 0) atomicAdd(&g_acc[1], (double)r);
    __syncthreads();
    r = blockReduce(accF, s_red);
    if (threadIdx.x == 0) atomicAdd(&g_acc[2], (double)r);
}

// ---------------------------------------------------------------------------
__global__ void cons_kernel(const float* __restrict__ lat,
                            const float* __restrict__ id, const float* __restrict__ td,
                            const float* __restrict__ mu, const float* __restrict__ lv)
{
    __shared__ float s_red[32];
    int i = blockIdx.x * blockDim.x + threadIdx.x;
    int stride = gridDim.x * blockDim.x;
    int b = i >> 8, z = i & 255;
    float d = lat[(size_t)(2 * b) * ZZ + z] - g_grad[i] - lat[(size_t)(2 * b + 1) * ZZ + z];
    float sc = d * d;
    float sd = 0.f, sk = 0.f;
    for (int k = i; k < BP * 2 * 3 * TT; k += stride) { float df = id[k] - td[k]; sd += df * df; }
    for (int k = i; k < N2 * ZZ; k += stride) {
        float m = mu[k], l = lv[k];
        sk += 1.0f + l - m * m - expf(l);
    }
    float r = blockReduce(sc, s_red);
    if (threadIdx.x == 0) atomicAdd(&g_acc[5], (double)r);
    __syncthreads();
    r = blockReduce(sd, s_red);
    if (threadIdx.x == 0) atomicAdd(&g_acc[4], (double)r);
    __syncthreads();
    r = blockReduce(sk, s_red);
    if (threadIdx.x == 0) atomicAdd(&g_acc[3], (double)r);
}

// ---------------------------------------------------------------------------
__global__ void finalize_kernel(float* out)
{
    out[0] = (float)(-0.5 * g_acc[3] / 1024.0) * 0.001f;
    out[1] = (float)(g_acc[0] / 524288.0);
    out[2] = (float)(g_acc[4] / 393216.0);
    out[3] = (float)(g_acc[5] / 131072.0) * 0.1f;
    out[4] = (float)(g_acc[2] / 9437184.0) * 0.1f;
    out[5] = (float)(g_acc[1] / 12058624.0);
}

// ---------------------------------------------------------------------------
extern "C" void kernel_launch(void* const* d_in, const int* in_sizes, int n_in,
                              void* d_out, int out_size)
{
    const float* base  = (const float*)d_in[0];
    const float* tgt   = (const float*)d_in[1];
    const float* idisp = (const float*)d_in[2];
    const float* tdisp = (const float*)d_in[3];
    const float* mu    = (const float*)d_in[4];
    const float* lv    = (const float*)d_in[5];
    const float* lat   = (const float*)d_in[6];
    const float* W     = (const float*)d_in[7];
    const float* meanq = (const float*)d_in[8];
    const float* stdq  = (const float*)d_in[9];
    const float* offs  = (const float*)d_in[10];
    float* out = (float*)d_out;

    cudaFuncSetAttribute(gemm1_tc, cudaFuncAttributeMaxDynamicSharedMemorySize, 37888);
    cudaFuncSetAttribute(gemm2_tc, cudaFuncAttributeMaxDynamicSharedMemorySize, 61440);
    cudaFuncSetAttribute(pose_kernel, cudaFuncAttributeMaxDynamicSharedMemorySize, 70656);

    cvt_kernel<<<12800, 256>>>(W, lat);
    gemm1_tc<<<dim3(96, 8), 256, 37888>>>(base);
    pose_kernel<<<BP, 256, 70656>>>(tgt, stdq, meanq, offs);
    gemm2_tc<<<dim3(2, 4, 32), 256, 61440>>>();
    cons_kernel<<<512, 256>>>(lat, idisp, tdisp, mu, lv);
    finalize_kernel<<<1, 1>>>(out);
}

// round 12
// speedup vs baseline: 1.3136x; 1.0330x over previous
#include <cuda_runtime.h>
#include <cuda_bf16.h>
#include <cstdint>

#define BP 512
#define CC 96
#define TT 128
#define JJ 24
#define ZZ 256
#define CT 12288
#define N2 1024

__device__ __nv_bfloat16  g_qsb[(size_t)N2 * CT];    // decoded motion bf16
__device__ __nv_bfloat16  g_dqsb[(size_t)BP * CT];   // d f / d qs (bf16)
__device__ float          g_grad[(size_t)BP * ZZ];   // grad wrt latent[:,0]
__device__ double         g_acc[6];                  // root joints fk kld disp cons
__device__ unsigned int   g_cnt;                     // cons arrival counter
__device__ __nv_bfloat16  g_W2[(size_t)ZZ * CT];     // W bf16, [z][ct]
__device__ uint32_t       g_W1[(size_t)(ZZ / 2) * CT]; // W bf16 k-pair packed [k2][n]
__device__ __nv_bfloat16  g_latb[(size_t)N2 * ZZ];   // latent bf16

// ---------------------------------------------------------------------------
// bf16 conversions (W two layouts + latent) with zero-init folded in
__global__ void cvt_kernel(const float* __restrict__ W, const float* __restrict__ lat)
{
    const int NW  = (ZZ * CT) / 2;
    const int NW1 = (ZZ / 2) * CT;
    const int NL  = (N2 * ZZ) / 2;
    int i = blockIdx.x * blockDim.x + threadIdx.x;
    if (i < BP * ZZ) g_grad[i] = 0.f;
    if (i < 6)       g_acc[i] = 0.0;
    if (i == 6)      g_cnt = 0u;
    if (i < NW) {
        float2 v = reinterpret_cast<const float2*>(W)[i];
        reinterpret_cast<__nv_bfloat162*>(g_W2)[i] = __floats2bfloat162_rn(v.x, v.y);
    } else if (i < NW + NW1) {
        int j = i - NW;
        int k2 = j / CT, n = j - k2 * CT;
        float lo = W[(size_t)(2 * k2) * CT + n];
        float hi = W[(size_t)(2 * k2 + 1) * CT + n];
        __nv_bfloat162 h = __floats2bfloat162_rn(lo, hi);
        g_W1[j] = *reinterpret_cast<uint32_t*>(&h);
    } else if (i < NW + NW1 + NL) {
        int j = i - NW - NW1;
        float2 v = reinterpret_cast<const float2*>(lat)[j];
        reinterpret_cast<__nv_bfloat162*>(g_latb)[j] = __floats2bfloat162_rn(v.x, v.y);
    }
}

// ---------------------------------------------------------------------------
__device__ __forceinline__ float blockReduce(float v, float* sm) {
#pragma unroll
    for (int o = 16; o > 0; o >>= 1) v += __shfl_down_sync(0xffffffffu, v, o);
    int lane = threadIdx.x & 31, w = threadIdx.x >> 5;
    if (lane == 0) sm[w] = v;
    __syncthreads();
    v = 0.f;
    if (threadIdx.x < 32) {
        int nw = (blockDim.x + 31) >> 5;
        v = (threadIdx.x < nw) ? sm[threadIdx.x] : 0.f;
#pragma unroll
        for (int o = 16; o > 0; o >>= 1) v += __shfl_down_sync(0xffffffffu, v, o);
    }
    return v;
}

// ---------------------------------------------------------------------------
__device__ __forceinline__ void cp16(uint32_t dst, const void* src) {
    asm volatile("cp.async.ca.shared.global [%0], [%1], 16;\n" :: "r"(dst), "l"(src));
}
#define CP_COMMIT() asm volatile("cp.async.commit_group;\n")
#define CP_WAIT1()  asm volatile("cp.async.wait_group 1;\n")

__device__ __forceinline__ void mma_bf16(float& c0, float& c1, float& c2, float& c3,
                                         uint32_t a0, uint32_t a1, uint32_t a2, uint32_t a3,
                                         uint32_t b0, uint32_t b1)
{
    asm volatile("mma.sync.aligned.m16n8k16.row.col.f32.bf16.bf16.f32 "
                 "{%0,%1,%2,%3}, {%4,%5,%6,%7}, {%8,%9}, {%0,%1,%2,%3};"
                 : "+f"(c0), "+f"(c1), "+f"(c2), "+f"(c3)
                 : "r"(a0), "r"(a1), "r"(a2), "r"(a3), "r"(b0), "r"(b1));
}

__device__ __forceinline__ void ldsm_x4(uint32_t* r, uint32_t addr) {
    asm volatile("ldmatrix.sync.aligned.m8n8.x4.shared.b16 {%0,%1,%2,%3}, [%4];"
                 : "=r"(r[0]), "=r"(r[1]), "=r"(r[2]), "=r"(r[3]) : "r"(addr));
}
__device__ __forceinline__ void ldsm_x2(uint32_t* r, uint32_t addr) {
    asm volatile("ldmatrix.sync.aligned.m8n8.x2.shared.b16 {%0,%1}, [%2];"
                 : "=r"(r[0]), "=r"(r[1]) : "r"(addr));
}

// ---------------------------------------------------------------------------
// GEMM1 (bf16 m16n8k16, cp.async 2-stage, A-frags via ldmatrix):
// g_qsb = latb(1024x256)@W1 + base (bf16 output)
__global__ __launch_bounds__(256, 2) void gemm1_tc(const float* __restrict__ base)
{
    extern __shared__ uint32_t smem[];
    uint32_t* AsU = smem;                 // 2 * 2560
    uint32_t* BsU = smem + 5120;          // 2 * 2176
    const uint32_t sA = (uint32_t)__cvta_generic_to_shared(AsU);
    const uint32_t sB = (uint32_t)__cvta_generic_to_shared(BsU);

    const int tid  = threadIdx.x;
    const int lane = tid & 31;
    const int wid  = tid >> 5;
    const int wm   = wid & 1;
    const int wn   = wid >> 1;
    const int g    = lane >> 2;
    const int tg   = lane & 3;
    const int bm   = blockIdx.y << 7;
    const int bn   = blockIdx.x << 7;

    const int lr       = lane & 7;
    const int rowShift = ((lane >> 3) & 1) << 3;
    const int kShift   = (lane >> 4) << 2;

    float acc[4][4][4];
#pragma unroll
    for (int i = 0; i < 4; i++)
#pragma unroll
        for (int j = 0; j < 4; j++)
#pragma unroll
            for (int c = 0; c < 4; c++) acc[i][j][c] = 0.f;

    auto loadTiles = [&](int kb, int s) {
#pragma unroll
        for (int it = 0; it < 2; it++) {
            int f = tid + it * 256;
            int m = f >> 2, cq = f & 3;
            cp16(sA + ((s * 2560 + m * 20 + cq * 4) << 2),
                 &g_latb[(size_t)(bm + m) * ZZ + kb + cq * 8]);
        }
        int kb2 = kb >> 1;
#pragma unroll
        for (int it = 0; it < 2; it++) {
            int f = tid + it * 256;
            int k2 = f >> 5, nq = f & 31;
            cp16(sB + ((s * 2176 + k2 * 136 + nq * 4) << 2),
                 &g_W1[(size_t)(kb2 + k2) * CT + bn + nq * 4]);
        }
    };

    loadTiles(0, 0);
    CP_COMMIT();

    const int NK = ZZ / 32;  // 8
    for (int kt = 0; kt < NK; kt++) {
        if (kt + 1 < NK) loadTiles((kt + 1) * 32, (kt + 1) & 1);
        CP_COMMIT();
        CP_WAIT1();
        __syncthreads();

        const uint32_t aStage = (kt & 1) * 2560;
        const uint32_t* bs = BsU + (kt & 1) * 2176;
#pragma unroll
        for (int ks = 0; ks < 2; ks++) {
            const int kc2 = ks * 8;
            uint32_t afr[4][4];
#pragma unroll
            for (int i = 0; i < 4; i++) {
                int r0b = wm * 64 + i * 16;
                uint32_t aw = aStage + (uint32_t)(r0b + lr + rowShift) * 20 + kc2 + kShift;
                ldsm_x4(afr[i], sA + (aw << 2));
            }
            uint32_t bfr[4][2];
#pragma unroll
            for (int j = 0; j < 4; j++) {
                int c0 = wn * 32 + j * 8 + g;
                bfr[j][0] = bs[(kc2 + tg) * 136 + c0];
                bfr[j][1] = bs[(kc2 + tg + 4) * 136 + c0];
            }
#pragma unroll
            for (int i = 0; i < 4; i++)
#pragma unroll
                for (int j = 0; j < 4; j++)
                    mma_bf16(acc[i][j][0], acc[i][j][1], acc[i][j][2], acc[i][j][3],
                             afr[i][0], afr[i][1], afr[i][2], afr[i][3],
                             bfr[j][0], bfr[j][1]);
        }
        __syncthreads();
    }

#pragma unroll
    for (int i = 0; i < 4; i++) {
#pragma unroll
        for (int j = 0; j < 4; j++) {
            int row0 = bm + wm * 64 + i * 16 + g;
            int col  = bn + wn * 32 + j * 8 + 2 * tg;
            {
                size_t o = (size_t)row0 * CT + col;
                float2 bv = *reinterpret_cast<const float2*>(&base[o]);
                *reinterpret_cast<__nv_bfloat162*>(&g_qsb[o]) =
                    __floats2bfloat162_rn(acc[i][j][0] + bv.x, acc[i][j][1] + bv.y);
            }
            {
                size_t o = (size_t)(row0 + 8) * CT + col;
                float2 bv = *reinterpret_cast<const float2*>(&base[o]);
                *reinterpret_cast<__nv_bfloat162*>(&g_qsb[o]) =
                    __floats2bfloat162_rn(acc[i][j][2] + bv.x, acc[i][j][3] + bv.y);
            }
        }
    }
}

// ---------------------------------------------------------------------------
// GEMM2 (bf16, cp.async 3-stage, split-K=32, full ldmatrix fragments)
__global__ __launch_bounds__(256, 2) void gemm2_tc()
{
    extern __shared__ uint32_t smem[];
    uint32_t* AsU = smem;                 // 3 * 2560
    uint32_t* WsU = smem + 7680;          // 3 * 2560
    const uint32_t sA = (uint32_t)__cvta_generic_to_shared(AsU);
    const uint32_t sW = (uint32_t)__cvta_generic_to_shared(WsU);

    const int tid  = threadIdx.x;
    const int lane = tid & 31;
    const int wid  = tid >> 5;
    const int wm   = wid & 1;
    const int wn   = wid >> 1;
    const int bm   = blockIdx.y << 7;
    const int bn   = blockIdx.x << 7;
    const int k0s  = blockIdx.z * (CT / 32);

    const int lr       = lane & 7;
    const int rowShift = ((lane >> 3) & 1) << 3;
    const int kShift   = (lane >> 4) << 2;
    const int selB     = ((lane >> 3) & 1) << 2;

    float acc[4][4][4];
#pragma unroll
    for (int i = 0; i < 4; i++)
#pragma unroll
        for (int j = 0; j < 4; j++)
#pragma unroll
            for (int c = 0; c < 4; c++) acc[i][j][c] = 0.f;

    auto loadTiles = [&](int kb, int s) {
#pragma unroll
        for (int it = 0; it < 2; it++) {
            int f = tid + it * 256;
            int m = f >> 2, cq = f & 3;
            cp16(sA + ((s * 2560 + m * 20 + cq * 4) << 2),
                 &g_dqsb[(size_t)(bm + m) * CT + kb + cq * 8]);
        }
#pragma unroll
        for (int it = 0; it < 2; it++) {
            int f = tid + it * 256;
            int z = f >> 2, cq = f & 3;
            cp16(sW + ((s * 2560 + z * 20 + cq * 4) << 2),
                 &g_W2[(size_t)(bn + z) * CT + kb + cq * 8]);
        }
    };

    loadTiles(k0s, 0);      CP_COMMIT();
    loadTiles(k0s + 32, 1); CP_COMMIT();

    const int NK = (CT / 32) / 32;  // 12
    int stage = 0;
    int lstage = 2;
    for (int kt = 0; kt < NK; kt++) {
        CP_WAIT1();
        __syncthreads();
        if (kt + 2 < NK) {
            loadTiles(k0s + (kt + 2) * 32, lstage);
            if (++lstage == 3) lstage = 0;
        }
        CP_COMMIT();

        const uint32_t base = stage * 2560;
        if (++stage == 3) stage = 0;
#pragma unroll
        for (int ks = 0; ks < 2; ks++) {
            const int kc2 = ks * 8;
            uint32_t afr[4][4];
#pragma unroll
            for (int i = 0; i < 4; i++) {
                int r0b = wm * 64 + i * 16;
                uint32_t aw = base + (uint32_t)(r0b + lr + rowShift) * 20 + kc2 + kShift;
                ldsm_x4(afr[i], sA + (aw << 2));
            }
            uint32_t bfr[4][2];
#pragma unroll
            for (int j = 0; j < 4; j++) {
                int c0b = wn * 32 + j * 8;
                uint32_t bw = base + (uint32_t)(c0b + lr) * 20 + kc2 + selB;
                ldsm_x2(bfr[j], sW + (bw << 2));
            }
#pragma unroll
            for (int i = 0; i < 4; i++)
#pragma unroll
                for (int j = 0; j < 4; j++)
                    mma_bf16(acc[i][j][0], acc[i][j][1], acc[i][j][2], acc[i][j][3],
                             afr[i][0], afr[i][1], afr[i][2], afr[i][3],
                             bfr[j][0], bfr[j][1]);
        }
    }

    const int g  = lane >> 2;
    const int tg = lane & 3;
#pragma unroll
    for (int i = 0; i < 4; i++)
#pragma unroll
        for (int j = 0; j < 4; j++) {
            int row0 = bm + wm * 64 + i * 16 + g;
            int col  = bn + wn * 32 + j * 8 + 2 * tg;
            atomicAdd(&g_grad[(size_t)row0 * ZZ + col],           acc[i][j][0]);
            atomicAdd(&g_grad[(size_t)row0 * ZZ + col + 1],       acc[i][j][1]);
            atomicAdd(&g_grad[(size_t)(row0 + 8) * ZZ + col],     acc[i][j][2]);
            atomicAdd(&g_grad[(size_t)(row0 + 8) * ZZ + col + 1], acc[i][j][3]);
        }
}

// ---------------------------------------------------------------------------
__device__ __forceinline__ void qrot(const float* __restrict__ q,
                                     const float* __restrict__ v,
                                     float* __restrict__ r)
{
    float w = q[0], x = q[1], y = q[2], z = q[3];
    float inv = 1.0f / (w * w + x * x + y * y + z * z);
    float a = w * w - (x * x + y * y + z * z);
    float d = 2.0f * (x * v[0] + y * v[1] + z * v[2]);
    float cx = y * v[2] - z * v[1];
    float cy = z * v[0] - x * v[2];
    float cz = x * v[1] - y * v[0];
    float tw = 2.0f * w;
    r[0] = (a * v[0] + d * x + tw * cx) * inv;
    r[1] = (a * v[1] + d * y + tw * cy) * inv;
    r[2] = (a * v[2] + d * z + tw * cz) * inv;
}

__device__ __forceinline__ void qrot_bwd(const float* __restrict__ q,
                                         const float* __restrict__ v,
                                         const float* __restrict__ g,
                                         float& dw, float& dx, float& dy, float& dz)
{
    float w = q[0], x = q[1], y = q[2], z = q[3];
    float inv = 1.0f / (w * w + x * x + y * y + z * z);
    float a = w * w - (x * x + y * y + z * z);
    float dd = 2.0f * (x * v[0] + y * v[1] + z * v[2]);
    float cx = y * v[2] - z * v[1];
    float cy = z * v[0] - x * v[2];
    float cz = x * v[1] - y * v[0];
    float tw = 2.0f * w;
    float r0 = (a * v[0] + dd * x + tw * cx) * inv;
    float r1 = (a * v[1] + dd * y + tw * cy) * inv;
    float r2 = (a * v[2] + dd * z + tw * cz) * inv;
    float c1 = v[0] * g[0] + v[1] * g[1] + v[2] * g[2];
    float c2 = x * g[0] + y * g[1] + z * g[2];
    float c3 = 0.5f * dd;
    float gr = g[0] * r0 + g[1] * r1 + g[2] * r2;
    float cg = cx * g[0] + cy * g[1] + cz * g[2];
    float s = 2.0f * inv;
    float vgx = v[1] * g[2] - v[2] * g[1];
    float vgy = v[2] * g[0] - v[0] * g[2];
    float vgz = v[0] * g[1] - v[1] * g[0];
    dw += s * (w * c1 + cg - w * gr);
    dx += s * (-c1 * x + c2 * v[0] + c3 * g[0] + w * vgx - gr * x);
    dy += s * (-c1 * y + c2 * v[1] + c3 * g[1] + w * vgy - gr * y);
    dz += s * (-c1 * z + c2 * v[2] + c3 * g[2] + w * vgz - gr * z);
}

// ---------------------------------------------------------------------------
// Pose kernel: k-split, pd in SMEM (69 rows x 256), qs read as bf16.
#define SPD(r) s_pd[((r) - 3) * 256]
__global__ __launch_bounds__(256, 3) void pose_kernel(const float* __restrict__ tgt,
                                                      const float* __restrict__ stdq,
                                                      const float* __restrict__ meanq,
                                                      const float* __restrict__ offs)
{
    extern __shared__ float s_pd[];          // 69*256 floats = 70656 B
    __shared__ float s_std[CC], s_mean[CC], s_off[JJ * 3];
    __shared__ float s_red[32];
    const int b  = blockIdx.x;
    const int t  = threadIdx.x;
    const int tk = t >> 7;
    const int tt = t & 127;
    if (t < CC) { s_std[t] = stdq[t]; s_mean[t] = meanq[t]; }
    if (t >= 128 && t < 128 + JJ * 3) s_off[t - 128] = offs[b * JJ * 3 + (t - 128)];
    __syncthreads();

    float accR = 0.f, accJ = 0.f, accF = 0.f;

    const __nv_bfloat16* dbase = g_qsb + (size_t)(b * 2 + tk) * CT + tt;
    const float* tbase = tgt + (size_t)(b * 2 + tk) * (2 * CT) + tt;

    {
#pragma unroll
        for (int i = 0; i < 4; i++) {
            float df = __bfloat162float(dbase[(size_t)i * TT]) - tbase[(size_t)i * TT];
            accR += df * df;
        }
        const int leaves[5] = { 10, 11, 15, 22, 23 };
#pragma unroll
        for (int e = 0; e < 5; e++) {
            int j = leaves[e];
#pragma unroll
            for (int i = 0; i < 4; i++) {
                float df = __bfloat162float(dbase[(size_t)(4 * j + i) * TT])
                         - tbase[(size_t)(8 * j + i) * TT];
                accJ += df * df;
            }
        }
    }

    // ---- FK forward (this k); decoded positions stored to SPD column t ----
    {
        float qD[4], qT[4];
        float pDx, pDy, pDz, pTx, pTy, pTz;

        auto loadPair = [&](int j) {
#pragma unroll
            for (int i = 0; i < 4; i++) {
                int c = 4 * j + i;
                float d  = __bfloat162float(dbase[(size_t)c * TT]);
                float tr = tbase[(size_t)(8 * j + i) * TT];
                float df = d - tr;
                accJ += df * df;
                qD[i] = d * s_std[c] + s_mean[c];
                qT[i] = tr * s_std[c] + s_mean[c];
            }
        };
        auto step = [&](int j) {
            const float* v = s_off + 3 * j;
            float r[3];
            qrot(qD, v, r); pDx += r[0]; pDy += r[1]; pDz += r[2];
            qrot(qT, v, r); pTx += r[0]; pTy += r[1]; pTz += r[2];
            float dx = pDx - pTx, dy = pDy - pTy, dz = pDz - pTz;
            accF += dx * dx + dy * dy + dz * dz;
            (&SPD(3 * j + 0))[t] = pDx;
            (&SPD(3 * j + 1))[t] = pDy;
            (&SPD(3 * j + 2))[t] = pDz;
        };
        auto reset = [&]() {
            pDx = pDy = pDz = pTx = pTy = pTz = 0.f;
            qD[0] = 1.f; qD[1] = qD[2] = qD[3] = 0.f;
            qT[0] = 1.f; qT[1] = qT[2] = qT[3] = 0.f;
        };

        reset();
        step(1); loadPair(1); step(4); loadPair(4); step(7); loadPair(7); step(10);
        reset();
        step(2); loadPair(2); step(5); loadPair(5); step(8); loadPair(8); step(11);
        reset();
        step(3); loadPair(3); step(6); loadPair(6); step(9); loadPair(9);
        float sp[6] = { pDx, pDy, pDz, pTx, pTy, pTz };
        float sqD[4] = { qD[0], qD[1], qD[2], qD[3] };
        float sqT[4] = { qT[0], qT[1], qT[2], qT[3] };
        step(12); loadPair(12); step(15);
        pDx = sp[0]; pDy = sp[1]; pDz = sp[2]; pTx = sp[3]; pTy = sp[4]; pTz = sp[5];
        qD[0] = sqD[0]; qD[1] = sqD[1]; qD[2] = sqD[2]; qD[3] = sqD[3];
        qT[0] = sqT[0]; qT[1] = sqT[1]; qT[2] = sqT[2]; qT[3] = sqT[3];
        step(13); loadPair(13); step(16); loadPair(16); step(18); loadPair(18);
        step(20); loadPair(20); step(22);
        pDx = sp[0]; pDy = sp[1]; pDz = sp[2]; pTx = sp[3]; pTy = sp[4]; pTz = sp[5];
        qD[0] = sqD[0]; qD[1] = sqD[1]; qD[2] = sqD[2]; qD[3] = sqD[3];
        qT[0] = sqT[0]; qT[1] = sqT[1]; qT[2] = sqT[2]; qT[3] = sqT[3];
        step(14); loadPair(14); step(17); loadPair(17); step(19); loadPair(19);
        step(21); loadPair(21); step(23);
    }
    __syncthreads();

    // ---- k=0 columns: upstream grad + adjoint accumulation in smem ----
    if (tk == 0) {
#pragma unroll
        for (int r = 3; r < 72; r++) {
            float* row = &SPD(r);
            float v = row[tt];
            row[tt] = 2.f * (v - row[tt + 128]);
        }
        const int ch[20] = { 23,22,21,20,19,18,17,16,15,14,13,12,11,10,9,8,7,6,5,4 };
        const int pa[20] = { 21,20,19,18,17,16,14,13,12, 9, 9, 9, 8, 7, 6, 5, 4, 3, 2, 1 };
#pragma unroll
        for (int e = 0; e < 20; e++) {
            int cj = ch[e], pj = pa[e];
#pragma unroll
            for (int i = 0; i < 3; i++)
                (&SPD(3 * pj + i))[tt] += (&SPD(3 * cj + i))[tt];
        }
    }
    __syncthreads();

    // ---- backward -> g_dqsb (split across halves) ----
    __nv_bfloat16* outp = g_dqsb + (size_t)b * CT + tt;
    const __nv_bfloat16* dbase0 = g_qsb + (size_t)(b * 2) * CT + tt;
    auto doParent = [&](int p, int c0, int c1, int c2) {
        float q[4];
#pragma unroll
        for (int i = 0; i < 4; i++) {
            int c = 4 * p + i;
            q[i] = __bfloat162float(dbase0[(size_t)c * TT]) * s_std[c] + s_mean[c];
        }
        float dw = 0.f, dx = 0.f, dy = 0.f, dz = 0.f;
        float gv[3];
        gv[0] = (&SPD(3 * c0 + 0))[tt];
        gv[1] = (&SPD(3 * c0 + 1))[tt];
        gv[2] = (&SPD(3 * c0 + 2))[tt];
        qrot_bwd(q, s_off + 3 * c0, gv, dw, dx, dy, dz);
        if (c1 >= 0) {
            gv[0] = (&SPD(3 * c1 + 0))[tt];
            gv[1] = (&SPD(3 * c1 + 1))[tt];
            gv[2] = (&SPD(3 * c1 + 2))[tt];
            qrot_bwd(q, s_off + 3 * c1, gv, dw, dx, dy, dz);
        }
        if (c2 >= 0) {
            gv[0] = (&SPD(3 * c2 + 0))[tt];
            gv[1] = (&SPD(3 * c2 + 1))[tt];
            gv[2] = (&SPD(3 * c2 + 2))[tt];
            qrot_bwd(q, s_off + 3 * c2, gv, dw, dx, dy, dz);
        }
        outp[(size_t)(4 * p + 0) * TT] = __float2bfloat16_rn(dw * s_std[4 * p + 0]);
        outp[(size_t)(4 * p + 1) * TT] = __float2bfloat16_rn(dx * s_std[4 * p + 1]);
        outp[(size_t)(4 * p + 2) * TT] = __float2bfloat16_rn(dy * s_std[4 * p + 2]);
        outp[(size_t)(4 * p + 3) * TT] = __float2bfloat16_rn(dz * s_std[4 * p + 3]);
    };
    const __nv_bfloat16 bz = __float2bfloat16_rn(0.f);
    if (tk == 0) {
        const int zj[3] = { 0, 10, 11 };
#pragma unroll
        for (int e = 0; e < 3; e++)
#pragma unroll
            for (int i = 0; i < 4; i++)
                outp[(size_t)(4 * zj[e] + i) * TT] = bz;
        doParent(1, 4, -1, -1);  doParent(2, 5, -1, -1);  doParent(3, 6, -1, -1);
        doParent(4, 7, -1, -1);  doParent(5, 8, -1, -1);  doParent(6, 9, -1, -1);
        doParent(7, 10, -1, -1); doParent(8, 11, -1, -1);
        doParent(9, 12, 13, 14);
    } else {
        const int zj[3] = { 15, 22, 23 };
#pragma unroll
        for (int e = 0; e < 3; e++)
#pragma unroll
            for (int i = 0; i < 4; i++)
                outp[(size_t)(4 * zj[e] + i) * TT] = bz;
        doParent(12, 15, -1, -1); doParent(13, 16, -1, -1); doParent(14, 17, -1, -1);
        doParent(16, 18, -1, -1); doParent(17, 19, -1, -1); doParent(18, 20, -1, -1);
        doParent(19, 21, -1, -1); doParent(20, 22, -1, -1); doParent(21, 23, -1, -1);
    }

    float r = blockReduce(accR, s_red);
    if (threadIdx.x == 0) atomicAdd(&g_acc[0], (double)r);
    __syncthreads();
    r = blockReduce(accJ, s_red);
    if (threadIdx.x == 0) atomicAdd(&g_acc[1], (double)r);
    __syncthreads();
    r = blockReduce(accF, s_red);
    if (threadIdx.x == 0) atomicAdd(&g_acc[2], (double)r);
}

// ---------------------------------------------------------------------------
// cons + disp + KLD reductions; last arriving block finalizes the output.
__global__ void cons_kernel(const float* __restrict__ lat,
                            const float* __restrict__ id, const float* __restrict__ td,
                            const float* __restrict__ mu, const float* __restrict__ lv,
                            float* __restrict__ out)
{
    __shared__ float s_red[32];
    int i = blockIdx.x * blockDim.x + threadIdx.x;
    int stride = gridDim.x * blockDim.x;
    int b = i >> 8, z = i & 255;
    float d = lat[(size_t)(2 * b) * ZZ + z] - g_grad[i] - lat[(size_t)(2 * b + 1) * ZZ + z];
    float sc = d * d;
    float sd = 0.f, sk = 0.f;
    for (int k = i; k < BP * 2 * 3 * TT; k += stride) { float df = id[k] - td[k]; sd += df * df; }
    for (int k = i; k < N2 * ZZ; k += stride) {
        float m = mu[k], l = lv[k];
        sk += 1.0f + l - m * m - expf(l);
    }
    float r = blockReduce(sc, s_red);
    if (threadIdx.x == 0) atomicAdd(&g_acc[5], (double)r);
    __syncthreads();
    r = blockReduce(sd, s_red);
    if (threadIdx.x == 0) atomicAdd(&g_acc[4], (double)r);
    __syncthreads();
    r = blockReduce(sk, s_red);
    if (threadIdx.x == 0) atomicAdd(&g_acc[3], (double)r);

    // finalize from the last block to arrive
    if (threadIdx.x == 0) {
        __threadfence();
        unsigned int c = atomicAdd(&g_cnt, 1u);
        if (c == gridDim.x - 1) {
            out[0] = (float)(-0.5 * g_acc[3] / 1024.0) * 0.001f;
            out[1] = (float)(g_acc[0] / 524288.0);
            out[2] = (float)(g_acc[4] / 393216.0);
            out[3] = (float)(g_acc[5] / 131072.0) * 0.1f;
            out[4] = (float)(g_acc[2] / 9437184.0) * 0.1f;
            out[5] = (float)(g_acc[1] / 12058624.0);
        }
    }
}

// ---------------------------------------------------------------------------
extern "C" void kernel_launch(void* const* d_in, const int* in_sizes, int n_in,
                              void* d_out, int out_size)
{
    const float* base  = (const float*)d_in[0];
    const float* tgt   = (const float*)d_in[1];
    const float* idisp = (const float*)d_in[2];
    const float* tdisp = (const float*)d_in[3];
    const float* mu    = (const float*)d_in[4];
    const float* lv    = (const float*)d_in[5];
    const float* lat   = (const float*)d_in[6];
    const float* W     = (const float*)d_in[7];
    const float* meanq = (const float*)d_in[8];
    const float* stdq  = (const float*)d_in[9];
    const float* offs  = (const float*)d_in[10];
    float* out = (float*)d_out;

    cudaFuncSetAttribute(gemm1_tc, cudaFuncAttributeMaxDynamicSharedMemorySize, 37888);
    cudaFuncSetAttribute(gemm2_tc, cudaFuncAttributeMaxDynamicSharedMemorySize, 61440);
    cudaFuncSetAttribute(pose_kernel, cudaFuncAttributeMaxDynamicSharedMemorySize, 70656);

    cvt_kernel<<<12800, 256>>>(W, lat);
    gemm1_tc<<<dim3(96, 8), 256, 37888>>>(base);
    pose_kernel<<<BP, 256, 70656>>>(tgt, stdq, meanq, offs);
    gemm2_tc<<<dim3(2, 4, 32), 256, 61440>>>();
    cons_kernel<<<512, 256>>>(lat, idisp, tdisp, mu, lv, out);
}

// round 13
// speedup vs baseline: 1.3334x; 1.0151x over previous
#include <cuda_runtime.h>
#include <cuda_bf16.h>
#include <cstdint>

#define BP 512
#define CC 96
#define TT 128
#define JJ 24
#define ZZ 256
#define CT 12288
#define N2 1024

__device__ __nv_bfloat16  g_qsb[(size_t)N2 * CT];    // decoded motion bf16
__device__ __nv_bfloat16  g_dqsb[(size_t)BP * CT];   // d f / d qs (bf16)
__device__ float          g_grad[(size_t)BP * ZZ];   // grad wrt latent[:,0]
__device__ double         g_acc[6];                  // root joints fk kld disp cons
__device__ unsigned int   g_cnt;                     // cons arrival counter
__device__ __nv_bfloat16  g_W2[(size_t)ZZ * CT];     // W bf16, [z][ct] (filled by gemm1)
__device__ uint32_t       g_W1[(size_t)(ZZ / 2) * CT]; // W bf16 k-pair packed [k2][n]
__device__ __nv_bfloat16  g_latb[(size_t)N2 * ZZ];   // latent bf16

// ---------------------------------------------------------------------------
// cvt: W1 (k-pair packed) + latent -> bf16, plus zero-init. (~13 MB traffic)
__global__ void cvt_kernel(const float* __restrict__ W, const float* __restrict__ lat)
{
    const int NW1 = (ZZ / 2) * CT;       // 1572864
    const int NL  = (N2 * ZZ) / 2;       // 131072
    int i = blockIdx.x * blockDim.x + threadIdx.x;
    if (i < BP * ZZ) g_grad[i] = 0.f;
    if (i < 6)       g_acc[i] = 0.0;
    if (i == 6)      g_cnt = 0u;
    if (i < NW1) {
        int k2 = i / CT, n = i - k2 * CT;
        float lo = W[(size_t)(2 * k2) * CT + n];
        float hi = W[(size_t)(2 * k2 + 1) * CT + n];
        __nv_bfloat162 h = __floats2bfloat162_rn(lo, hi);
        g_W1[i] = *reinterpret_cast<uint32_t*>(&h);
    } else if (i < NW1 + NL) {
        int j = i - NW1;
        float2 v = reinterpret_cast<const float2*>(lat)[j];
        reinterpret_cast<__nv_bfloat162*>(g_latb)[j] = __floats2bfloat162_rn(v.x, v.y);
    }
}

// ---------------------------------------------------------------------------
__device__ __forceinline__ float blockReduce(float v, float* sm) {
#pragma unroll
    for (int o = 16; o > 0; o >>= 1) v += __shfl_down_sync(0xffffffffu, v, o);
    int lane = threadIdx.x & 31, w = threadIdx.x >> 5;
    if (lane == 0) sm[w] = v;
    __syncthreads();
    v = 0.f;
    if (threadIdx.x < 32) {
        int nw = (blockDim.x + 31) >> 5;
        v = (threadIdx.x < nw) ? sm[threadIdx.x] : 0.f;
#pragma unroll
        for (int o = 16; o > 0; o >>= 1) v += __shfl_down_sync(0xffffffffu, v, o);
    }
    return v;
}

// ---------------------------------------------------------------------------
__device__ __forceinline__ void cp16(uint32_t dst, const void* src) {
    asm volatile("cp.async.ca.shared.global [%0], [%1], 16;\n" :: "r"(dst), "l"(src));
}
#define CP_COMMIT() asm volatile("cp.async.commit_group;\n")
#define CP_WAIT1()  asm volatile("cp.async.wait_group 1;\n")

__device__ __forceinline__ void mma_bf16(float& c0, float& c1, float& c2, float& c3,
                                         uint32_t a0, uint32_t a1, uint32_t a2, uint32_t a3,
                                         uint32_t b0, uint32_t b1)
{
    asm volatile("mma.sync.aligned.m16n8k16.row.col.f32.bf16.bf16.f32 "
                 "{%0,%1,%2,%3}, {%4,%5,%6,%7}, {%8,%9}, {%0,%1,%2,%3};"
                 : "+f"(c0), "+f"(c1), "+f"(c2), "+f"(c3)
                 : "r"(a0), "r"(a1), "r"(a2), "r"(a3), "r"(b0), "r"(b1));
}

__device__ __forceinline__ void ldsm_x4(uint32_t* r, uint32_t addr) {
    asm volatile("ldmatrix.sync.aligned.m8n8.x4.shared.b16 {%0,%1,%2,%3}, [%4];"
                 : "=r"(r[0]), "=r"(r[1]), "=r"(r[2]), "=r"(r[3]) : "r"(addr));
}
__device__ __forceinline__ void ldsm_x2(uint32_t* r, uint32_t addr) {
    asm volatile("ldmatrix.sync.aligned.m8n8.x2.shared.b16 {%0,%1}, [%2];"
                 : "=r"(r[0]), "=r"(r[1]) : "r"(addr));
}

// ---------------------------------------------------------------------------
// GEMM1 (bf16 m16n8k16, cp.async 2-stage, A-frags via ldmatrix):
// g_qsb = latb(1024x256)@W1 + base. Also converts W -> g_W2 (for gemm2).
__global__ __launch_bounds__(256, 2) void gemm1_tc(const float* __restrict__ base,
                                                   const float* __restrict__ W)
{
    extern __shared__ uint32_t smem[];
    uint32_t* AsU = smem;                 // 2 * 2560
    uint32_t* BsU = smem + 5120;          // 2 * 2176
    const uint32_t sA = (uint32_t)__cvta_generic_to_shared(AsU);
    const uint32_t sB = (uint32_t)__cvta_generic_to_shared(BsU);

    const int tid  = threadIdx.x;
    const int lane = tid & 31;
    const int wid  = tid >> 5;
    const int wm   = wid & 1;
    const int wn   = wid >> 1;
    const int g    = lane >> 2;
    const int tg   = lane & 3;
    const int bm   = blockIdx.y << 7;
    const int bn   = blockIdx.x << 7;

    const int lr       = lane & 7;
    const int rowShift = ((lane >> 3) & 1) << 3;
    const int kShift   = (lane >> 4) << 2;

    float acc[4][4][4];
#pragma unroll
    for (int i = 0; i < 4; i++)
#pragma unroll
        for (int j = 0; j < 4; j++)
#pragma unroll
            for (int c = 0; c < 4; c++) acc[i][j][c] = 0.f;

    auto loadTiles = [&](int kb, int s) {
#pragma unroll
        for (int it = 0; it < 2; it++) {
            int f = tid + it * 256;
            int m = f >> 2, cq = f & 3;
            cp16(sA + ((s * 2560 + m * 20 + cq * 4) << 2),
                 &g_latb[(size_t)(bm + m) * ZZ + kb + cq * 8]);
        }
        int kb2 = kb >> 1;
#pragma unroll
        for (int it = 0; it < 2; it++) {
            int f = tid + it * 256;
            int k2 = f >> 5, nq = f & 31;
            cp16(sB + ((s * 2176 + k2 * 136 + nq * 4) << 2),
                 &g_W1[(size_t)(kb2 + k2) * CT + bn + nq * 4]);
        }
    };

    loadTiles(0, 0);
    CP_COMMIT();

    // --- absorbed: convert W -> g_W2 (bf16) while pipeline warms up ---
    {
        const int NW = (ZZ * CT) / 2;                       // float2 pairs
        int flat = (blockIdx.y * gridDim.x + blockIdx.x) * 256 + tid;
        const int stride = gridDim.x * gridDim.y * 256;     // 196608
        for (int p = flat; p < NW; p += stride) {
            float2 v = reinterpret_cast<const float2*>(W)[p];
            reinterpret_cast<__nv_bfloat162*>(g_W2)[p] = __floats2bfloat162_rn(v.x, v.y);
        }
    }

    const int NK = ZZ / 32;  // 8
    for (int kt = 0; kt < NK; kt++) {
        if (kt + 1 < NK) loadTiles((kt + 1) * 32, (kt + 1) & 1);
        CP_COMMIT();
        CP_WAIT1();
        __syncthreads();

        const uint32_t aStage = (kt & 1) * 2560;
        const uint32_t* bs = BsU + (kt & 1) * 2176;
#pragma unroll
        for (int ks = 0; ks < 2; ks++) {
            const int kc2 = ks * 8;
            uint32_t afr[4][4];
#pragma unroll
            for (int i = 0; i < 4; i++) {
                int r0b = wm * 64 + i * 16;
                uint32_t aw = aStage + (uint32_t)(r0b + lr + rowShift) * 20 + kc2 + kShift;
                ldsm_x4(afr[i], sA + (aw << 2));
            }
            uint32_t bfr[4][2];
#pragma unroll
            for (int j = 0; j < 4; j++) {
                int c0 = wn * 32 + j * 8 + g;
                bfr[j][0] = bs[(kc2 + tg) * 136 + c0];
                bfr[j][1] = bs[(kc2 + tg + 4) * 136 + c0];
            }
#pragma unroll
            for (int i = 0; i < 4; i++)
#pragma unroll
                for (int j = 0; j < 4; j++)
                    mma_bf16(acc[i][j][0], acc[i][j][1], acc[i][j][2], acc[i][j][3],
                             afr[i][0], afr[i][1], afr[i][2], afr[i][3],
                             bfr[j][0], bfr[j][1]);
        }
        __syncthreads();
    }

#pragma unroll
    for (int i = 0; i < 4; i++) {
#pragma unroll
        for (int j = 0; j < 4; j++) {
            int row0 = bm + wm * 64 + i * 16 + g;
            int col  = bn + wn * 32 + j * 8 + 2 * tg;
            {
                size_t o = (size_t)row0 * CT + col;
                float2 bv = *reinterpret_cast<const float2*>(&base[o]);
                *reinterpret_cast<__nv_bfloat162*>(&g_qsb[o]) =
                    __floats2bfloat162_rn(acc[i][j][0] + bv.x, acc[i][j][1] + bv.y);
            }
            {
                size_t o = (size_t)(row0 + 8) * CT + col;
                float2 bv = *reinterpret_cast<const float2*>(&base[o]);
                *reinterpret_cast<__nv_bfloat162*>(&g_qsb[o]) =
                    __floats2bfloat162_rn(acc[i][j][2] + bv.x, acc[i][j][3] + bv.y);
            }
        }
    }
}

// ---------------------------------------------------------------------------
// GEMM2 (bf16, cp.async 3-stage, split-K=32, ldmatrix fragments).
// Also absorbs the disp-MSE and KLD reductions in its prologue.
__global__ __launch_bounds__(256, 2) void gemm2_tc(const float* __restrict__ id,
                                                   const float* __restrict__ td,
                                                   const float* __restrict__ mu,
                                                   const float* __restrict__ lv)
{
    extern __shared__ uint32_t smem[];
    __shared__ float s_red[32];
    uint32_t* AsU = smem;                 // 3 * 2560
    uint32_t* WsU = smem + 7680;          // 3 * 2560
    const uint32_t sA = (uint32_t)__cvta_generic_to_shared(AsU);
    const uint32_t sW = (uint32_t)__cvta_generic_to_shared(WsU);

    const int tid  = threadIdx.x;
    const int lane = tid & 31;
    const int wid  = tid >> 5;
    const int wm   = wid & 1;
    const int wn   = wid >> 1;
    const int bm   = blockIdx.y << 7;
    const int bn   = blockIdx.x << 7;
    const int k0s  = blockIdx.z * (CT / 32);

    const int lr       = lane & 7;
    const int rowShift = ((lane >> 3) & 1) << 3;
    const int kShift   = (lane >> 4) << 2;
    const int selB     = ((lane >> 3) & 1) << 2;

    float acc[4][4][4];
#pragma unroll
    for (int i = 0; i < 4; i++)
#pragma unroll
        for (int j = 0; j < 4; j++)
#pragma unroll
            for (int c = 0; c < 4; c++) acc[i][j][c] = 0.f;

    auto loadTiles = [&](int kb, int s) {
#pragma unroll
        for (int it = 0; it < 2; it++) {
            int f = tid + it * 256;
            int m = f >> 2, cq = f & 3;
            cp16(sA + ((s * 2560 + m * 20 + cq * 4) << 2),
                 &g_dqsb[(size_t)(bm + m) * CT + kb + cq * 8]);
        }
#pragma unroll
        for (int it = 0; it < 2; it++) {
            int f = tid + it * 256;
            int z = f >> 2, cq = f & 3;
            cp16(sW + ((s * 2560 + z * 20 + cq * 4) << 2),
                 &g_W2[(size_t)(bn + z) * CT + kb + cq * 8]);
        }
    };

    loadTiles(k0s, 0);      CP_COMMIT();
    loadTiles(k0s + 32, 1); CP_COMMIT();

    // --- absorbed: disp MSE + KLD (independent of GEMM data) ---
    {
        int flat = ((blockIdx.z * gridDim.y + blockIdx.y) * gridDim.x + blockIdx.x) * 256 + tid;
        const int stride = gridDim.x * gridDim.y * gridDim.z * 256;  // 65536
        float sd = 0.f, sk = 0.f;
        for (int k = flat; k < BP * 2 * 3 * TT; k += stride) {
            float df = id[k] - td[k]; sd += df * df;
        }
        for (int k = flat; k < N2 * ZZ; k += stride) {
            float m = mu[k], l = lv[k];
            sk += 1.0f + l - m * m - expf(l);
        }
        float r = blockReduce(sd, s_red);
        if (tid == 0) atomicAdd(&g_acc[4], (double)r);
        __syncthreads();
        r = blockReduce(sk, s_red);
        if (tid == 0) atomicAdd(&g_acc[3], (double)r);
    }

    const int NK = (CT / 32) / 32;  // 12
    int stage = 0;
    int lstage = 2;
    for (int kt = 0; kt < NK; kt++) {
        CP_WAIT1();
        __syncthreads();
        if (kt + 2 < NK) {
            loadTiles(k0s + (kt + 2) * 32, lstage);
            if (++lstage == 3) lstage = 0;
        }
        CP_COMMIT();

        const uint32_t base = stage * 2560;
        if (++stage == 3) stage = 0;
#pragma unroll
        for (int ks = 0; ks < 2; ks++) {
            const int kc2 = ks * 8;
            uint32_t afr[4][4];
#pragma unroll
            for (int i = 0; i < 4; i++) {
                int r0b = wm * 64 + i * 16;
                uint32_t aw = base + (uint32_t)(r0b + lr + rowShift) * 20 + kc2 + kShift;
                ldsm_x4(afr[i], sA + (aw << 2));
            }
            uint32_t bfr[4][2];
#pragma unroll
            for (int j = 0; j < 4; j++) {
                int c0b = wn * 32 + j * 8;
                uint32_t bw = base + (uint32_t)(c0b + lr) * 20 + kc2 + selB;
                ldsm_x2(bfr[j], sW + (bw << 2));
            }
#pragma unroll
            for (int i = 0; i < 4; i++)
#pragma unroll
                for (int j = 0; j < 4; j++)
                    mma_bf16(acc[i][j][0], acc[i][j][1], acc[i][j][2], acc[i][j][3],
                             afr[i][0], afr[i][1], afr[i][2], afr[i][3],
                             bfr[j][0], bfr[j][1]);
        }
    }

    const int g  = lane >> 2;
    const int tg = lane & 3;
#pragma unroll
    for (int i = 0; i < 4; i++)
#pragma unroll
        for (int j = 0; j < 4; j++) {
            int row0 = bm + wm * 64 + i * 16 + g;
            int col  = bn + wn * 32 + j * 8 + 2 * tg;
            atomicAdd(&g_grad[(size_t)row0 * ZZ + col],           acc[i][j][0]);
            atomicAdd(&g_grad[(size_t)row0 * ZZ + col + 1],       acc[i][j][1]);
            atomicAdd(&g_grad[(size_t)(row0 + 8) * ZZ + col],     acc[i][j][2]);
            atomicAdd(&g_grad[(size_t)(row0 + 8) * ZZ + col + 1], acc[i][j][3]);
        }
}

// ---------------------------------------------------------------------------
__device__ __forceinline__ void qrot(const float* __restrict__ q,
                                     const float* __restrict__ v,
                                     float* __restrict__ r)
{
    float w = q[0], x = q[1], y = q[2], z = q[3];
    float inv = 1.0f / (w * w + x * x + y * y + z * z);
    float a = w * w - (x * x + y * y + z * z);
    float d = 2.0f * (x * v[0] + y * v[1] + z * v[2]);
    float cx = y * v[2] - z * v[1];
    float cy = z * v[0] - x * v[2];
    float cz = x * v[1] - y * v[0];
    float tw = 2.0f * w;
    r[0] = (a * v[0] + d * x + tw * cx) * inv;
    r[1] = (a * v[1] + d * y + tw * cy) * inv;
    r[2] = (a * v[2] + d * z + tw * cz) * inv;
}

__device__ __forceinline__ void qrot_bwd(const float* __restrict__ q,
                                         const float* __restrict__ v,
                                         const float* __restrict__ g,
                                         float& dw, float& dx, float& dy, float& dz)
{
    float w = q[0], x = q[1], y = q[2], z = q[3];
    float inv = 1.0f / (w * w + x * x + y * y + z * z);
    float a = w * w - (x * x + y * y + z * z);
    float dd = 2.0f * (x * v[0] + y * v[1] + z * v[2]);
    float cx = y * v[2] - z * v[1];
    float cy = z * v[0] - x * v[2];
    float cz = x * v[1] - y * v[0];
    float tw = 2.0f * w;
    float r0 = (a * v[0] + dd * x + tw * cx) * inv;
    float r1 = (a * v[1] + dd * y + tw * cy) * inv;
    float r2 = (a * v[2] + dd * z + tw * cz) * inv;
    float c1 = v[0] * g[0] + v[1] * g[1] + v[2] * g[2];
    float c2 = x * g[0] + y * g[1] + z * g[2];
    float c3 = 0.5f * dd;
    float gr = g[0] * r0 + g[1] * r1 + g[2] * r2;
    float cg = cx * g[0] + cy * g[1] + cz * g[2];
    float s = 2.0f * inv;
    float vgx = v[1] * g[2] - v[2] * g[1];
    float vgy = v[2] * g[0] - v[0] * g[2];
    float vgz = v[0] * g[1] - v[1] * g[0];
    dw += s * (w * c1 + cg - w * gr);
    dx += s * (-c1 * x + c2 * v[0] + c3 * g[0] + w * vgx - gr * x);
    dy += s * (-c1 * y + c2 * v[1] + c3 * g[1] + w * vgy - gr * y);
    dz += s * (-c1 * z + c2 * v[2] + c3 * g[2] + w * vgz - gr * z);
}

// ---------------------------------------------------------------------------
// Pose kernel: k-split, pd in SMEM (69 rows x 256), qs read as bf16.
#define SPD(r) s_pd[((r) - 3) * 256]
__global__ __launch_bounds__(256, 3) void pose_kernel(const float* __restrict__ tgt,
                                                      const float* __restrict__ stdq,
                                                      const float* __restrict__ meanq,
                                                      const float* __restrict__ offs)
{
    extern __shared__ float s_pd[];          // 69*256 floats
    __shared__ float s_std[CC], s_mean[CC], s_off[JJ * 3];
    __shared__ float s_red[32];
    const int b  = blockIdx.x;
    const int t  = threadIdx.x;
    const int tk = t >> 7;
    const int tt = t & 127;
    if (t < CC) { s_std[t] = stdq[t]; s_mean[t] = meanq[t]; }
    if (t >= 128 && t < 128 + JJ * 3) s_off[t - 128] = offs[b * JJ * 3 + (t - 128)];
    __syncthreads();

    float accR = 0.f, accJ = 0.f, accF = 0.f;

    const __nv_bfloat16* dbase = g_qsb + (size_t)(b * 2 + tk) * CT + tt;
    const float* tbase = tgt + (size_t)(b * 2 + tk) * (2 * CT) + tt;

    {
#pragma unroll
        for (int i = 0; i < 4; i++) {
            float df = __bfloat162float(dbase[(size_t)i * TT]) - tbase[(size_t)i * TT];
            accR += df * df;
        }
        const int leaves[5] = { 10, 11, 15, 22, 23 };
#pragma unroll
        for (int e = 0; e < 5; e++) {
            int j = leaves[e];
#pragma unroll
            for (int i = 0; i < 4; i++) {
                float df = __bfloat162float(dbase[(size_t)(4 * j + i) * TT])
                         - tbase[(size_t)(8 * j + i) * TT];
                accJ += df * df;
            }
        }
    }

    {
        float qD[4], qT[4];
        float pDx, pDy, pDz, pTx, pTy, pTz;

        auto loadPair = [&](int j) {
#pragma unroll
            for (int i = 0; i < 4; i++) {
                int c = 4 * j + i;
                float d  = __bfloat162float(dbase[(size_t)c * TT]);
                float tr = tbase[(size_t)(8 * j + i) * TT];
                float df = d - tr;
                accJ += df * df;
                qD[i] = d * s_std[c] + s_mean[c];
                qT[i] = tr * s_std[c] + s_mean[c];
            }
        };
        auto step = [&](int j) {
            const float* v = s_off + 3 * j;
            float r[3];
            qrot(qD, v, r); pDx += r[0]; pDy += r[1]; pDz += r[2];
            qrot(qT, v, r); pTx += r[0]; pTy += r[1]; pTz += r[2];
            float dx = pDx - pTx, dy = pDy - pTy, dz = pDz - pTz;
            accF += dx * dx + dy * dy + dz * dz;
            (&SPD(3 * j + 0))[t] = pDx;
            (&SPD(3 * j + 1))[t] = pDy;
            (&SPD(3 * j + 2))[t] = pDz;
        };
        auto reset = [&]() {
            pDx = pDy = pDz = pTx = pTy = pTz = 0.f;
            qD[0] = 1.f; qD[1] = qD[2] = qD[3] = 0.f;
            qT[0] = 1.f; qT[1] = qT[2] = qT[3] = 0.f;
        };

        reset();
        step(1); loadPair(1); step(4); loadPair(4); step(7); loadPair(7); step(10);
        reset();
        step(2); loadPair(2); step(5); loadPair(5); step(8); loadPair(8); step(11);
        reset();
        step(3); loadPair(3); step(6); loadPair(6); step(9); loadPair(9);
        float sp[6] = { pDx, pDy, pDz, pTx, pTy, pTz };
        float sqD[4] = { qD[0], qD[1], qD[2], qD[3] };
        float sqT[4] = { qT[0], qT[1], qT[2], qT[3] };
        step(12); loadPair(12); step(15);
        pDx = sp[0]; pDy = sp[1]; pDz = sp[2]; pTx = sp[3]; pTy = sp[4]; pTz = sp[5];
        qD[0] = sqD[0]; qD[1] = sqD[1]; qD[2] = sqD[2]; qD[3] = sqD[3];
        qT[0] = sqT[0]; qT[1] = sqT[1]; qT[2] = sqT[2]; qT[3] = sqT[3];
        step(13); loadPair(13); step(16); loadPair(16); step(18); loadPair(18);
        step(20); loadPair(20); step(22);
        pDx = sp[0]; pDy = sp[1]; pDz = sp[2]; pTx = sp[3]; pTy = sp[4]; pTz = sp[5];
        qD[0] = sqD[0]; qD[1] = sqD[1]; qD[2] = sqD[2]; qD[3] = sqD[3];
        qT[0] = sqT[0]; qT[1] = sqT[1]; qT[2] = sqT[2]; qT[3] = sqT[3];
        step(14); loadPair(14); step(17); loadPair(17); step(19); loadPair(19);
        step(21); loadPair(21); step(23);
    }
    __syncthreads();

    if (tk == 0) {
#pragma unroll
        for (int r = 3; r < 72; r++) {
            float* row = &SPD(r);
            float v = row[tt];
            row[tt] = 2.f * (v - row[tt + 128]);
        }
        const int ch[20] = { 23,22,21,20,19,18,17,16,15,14,13,12,11,10,9,8,7,6,5,4 };
        const int pa[20] = { 21,20,19,18,17,16,14,13,12, 9, 9, 9, 8, 7, 6, 5, 4, 3, 2, 1 };
#pragma unroll
        for (int e = 0; e < 20; e++) {
            int cj = ch[e], pj = pa[e];
#pragma unroll
            for (int i = 0; i < 3; i++)
                (&SPD(3 * pj + i))[tt] += (&SPD(3 * cj + i))[tt];
        }
    }
    __syncthreads();

    __nv_bfloat16* outp = g_dqsb + (size_t)b * CT + tt;
    const __nv_bfloat16* dbase0 = g_qsb + (size_t)(b * 2) * CT + tt;
    auto doParent = [&](int p, int c0, int c1, int c2) {
        float q[4];
#pragma unroll
        for (int i = 0; i < 4; i++) {
            int c = 4 * p + i;
            q[i] = __bfloat162float(dbase0[(size_t)c * TT]) * s_std[c] + s_mean[c];
        }
        float dw = 0.f, dx = 0.f, dy = 0.f, dz = 0.f;
        float gv[3];
        gv[0] = (&SPD(3 * c0 + 0))[tt];
        gv[1] = (&SPD(3 * c0 + 1))[tt];
        gv[2] = (&SPD(3 * c0 + 2))[tt];
        qrot_bwd(q, s_off + 3 * c0, gv, dw, dx, dy, dz);
        if (c1 >= 0) {
            gv[0] = (&SPD(3 * c1 + 0))[tt];
            gv[1] = (&SPD(3 * c1 + 1))[tt];
            gv[2] = (&SPD(3 * c1 + 2))[tt];
            qrot_bwd(q, s_off + 3 * c1, gv, dw, dx, dy, dz);
        }
        if (c2 >= 0) {
            gv[0] = (&SPD(3 * c2 + 0))[tt];
            gv[1] = (&SPD(3 * c2 + 1))[tt];
            gv[2] = (&SPD(3 * c2 + 2))[tt];
            qrot_bwd(q, s_off + 3 * c2, gv, dw, dx, dy, dz);
        }
        outp[(size_t)(4 * p + 0) * TT] = __float2bfloat16_rn(dw * s_std[4 * p + 0]);
        outp[(size_t)(4 * p + 1) * TT] = __float2bfloat16_rn(dx * s_std[4 * p + 1]);
        outp[(size_t)(4 * p + 2) * TT] = __float2bfloat16_rn(dy * s_std[4 * p + 2]);
        outp[(size_t)(4 * p + 3) * TT] = __float2bfloat16_rn(dz * s_std[4 * p + 3]);
    };
    const __nv_bfloat16 bz = __float2bfloat16_rn(0.f);
    if (tk == 0) {
        const int zj[3] = { 0, 10, 11 };
#pragma unroll
        for (int e = 0; e < 3; e++)
#pragma unroll
            for (int i = 0; i < 4; i++)
                outp[(size_t)(4 * zj[e] + i) * TT] = bz;
        doParent(1, 4, -1, -1);  doParent(2, 5, -1, -1);  doParent(3, 6, -1, -1);
        doParent(4, 7, -1, -1);  doParent(5, 8, -1, -1);  doParent(6, 9, -1, -1);
        doParent(7, 10, -1, -1); doParent(8, 11, -1, -1);
        doParent(9, 12, 13, 14);
    } else {
        const int zj[3] = { 15, 22, 23 };
#pragma unroll
        for (int e = 0; e < 3; e++)
#pragma unroll
            for (int i = 0; i < 4; i++)
                outp[(size_t)(4 * zj[e] + i) * TT] = bz;
        doParent(12, 15, -1, -1); doParent(13, 16, -1, -1); doParent(14, 17, -1, -1);
        doParent(16, 18, -1, -1); doParent(17, 19, -1, -1); doParent(18, 20, -1, -1);
        doParent(19, 21, -1, -1); doParent(20, 22, -1, -1); doParent(21, 23, -1, -1);
    }

    float r = blockReduce(accR, s_red);
    if (threadIdx.x == 0) atomicAdd(&g_acc[0], (double)r);
    __syncthreads();
    r = blockReduce(accJ, s_red);
    if (threadIdx.x == 0) atomicAdd(&g_acc[1], (double)r);
    __syncthreads();
    r = blockReduce(accF, s_red);
    if (threadIdx.x == 0) atomicAdd(&g_acc[2], (double)r);
}

// ---------------------------------------------------------------------------
// cons loss only; last arriving block finalizes the output.
__global__ void cons_kernel(const float* __restrict__ lat, float* __restrict__ out)
{
    __shared__ float s_red[32];
    int i = blockIdx.x * blockDim.x + threadIdx.x;
    int b = i >> 8, z = i & 255;
    float d = lat[(size_t)(2 * b) * ZZ + z] - g_grad[i] - lat[(size_t)(2 * b + 1) * ZZ + z];
    float r = blockReduce(d * d, s_red);
    if (threadIdx.x == 0) atomicAdd(&g_acc[5], (double)r);

    if (threadIdx.x == 0) {
        __threadfence();
        unsigned int c = atomicAdd(&g_cnt, 1u);
        if (c == gridDim.x - 1) {
            out[0] = (float)(-0.5 * g_acc[3] / 1024.0) * 0.001f;
            out[1] = (float)(g_acc[0] / 524288.0);
            out[2] = (float)(g_acc[4] / 393216.0);
            out[3] = (float)(g_acc[5] / 131072.0) * 0.1f;
            out[4] = (float)(g_acc[2] / 9437184.0) * 0.1f;
            out[5] = (float)(g_acc[1] / 12058624.0);
        }
    }
}

// ---------------------------------------------------------------------------
extern "C" void kernel_launch(void* const* d_in, const int* in_sizes, int n_in,
                              void* d_out, int out_size)
{
    const float* base  = (const float*)d_in[0];
    const float* tgt   = (const float*)d_in[1];
    const float* idisp = (const float*)d_in[2];
    const float* tdisp = (const float*)d_in[3];
    const float* mu    = (const float*)d_in[4];
    const float* lv    = (const float*)d_in[5];
    const float* lat   = (const float*)d_in[6];
    const float* W     = (const float*)d_in[7];
    const float* meanq = (const float*)d_in[8];
    const float* stdq  = (const float*)d_in[9];
    const float* offs  = (const float*)d_in[10];
    float* out = (float*)d_out;

    cudaFuncSetAttribute(gemm1_tc, cudaFuncAttributeMaxDynamicSharedMemorySize, 37888);
    cudaFuncSetAttribute(gemm2_tc, cudaFuncAttributeMaxDynamicSharedMemorySize, 61440);
    cudaFuncSetAttribute(pose_kernel, cudaFuncAttributeMaxDynamicSharedMemorySize, 70656);

    cvt_kernel<<<6657, 256>>>(W, lat);
    gemm1_tc<<<dim3(96, 8), 256, 37888>>>(base, W);
    pose_kernel<<<BP, 256, 70656>>>(tgt, stdq, meanq, offs);
    gemm2_tc<<<dim3(2, 4, 32), 256, 61440>>>(idisp, tdisp, mu, lv);
    cons_kernel<<<512, 256>>>(lat, out);
}